// round 6
// baseline (speedup 1.0000x reference)
#include <cuda_runtime.h>
#include <math.h>
#include <stdint.h>

// ---------------- problem constants ----------------
#define CDIM    384
#define NHEAD   12
#define TOK     100352        // 32*3136
#define EPS     1e-5f
#define SCALE   0.17677669529663687f  // 1/sqrt(32)

// ---------------- scratch (device globals; no allocations) ----------------
__device__ float g_h  [(size_t)TOK * 384];
__device__ float g_qkv[(size_t)TOK * 1152];
__device__ float g_o  [(size_t)TOK * 384];
__device__ float g_xa [(size_t)TOK * 384];
__device__ float g_y  [(size_t)TOK * 384];
__device__ float g_u  [(size_t)TOK * 1536];
__device__ float g_wt [1769472];              // transposed+rounded weights

#define WT_QKV 0
#define WT_PROJ 442368
#define WT_FC1 589824
#define WT_FC2 1179648

// ---------------- small PTX helpers ----------------
__device__ __forceinline__ uint32_t smem_u32(const void* p){
    uint32_t a;
    asm("{ .reg .u64 t; cvta.to.shared.u64 t, %1; cvt.u32.u64 %0, t; }" : "=r"(a) : "l"(p));
    return a;
}
__device__ __forceinline__ float tf32r(float f){
    uint32_t r; asm("cvt.rna.tf32.f32 %0, %1;" : "=r"(r) : "f"(f));
    return __uint_as_float(r);
}
__device__ __forceinline__ void cp16(uint32_t d, const void* s){
    asm volatile("cp.async.cg.shared.global [%0], [%1], 16;" :: "r"(d), "l"(s));
}
__device__ __forceinline__ void cp_commit(){ asm volatile("cp.async.commit_group;"); }
__device__ __forceinline__ void cp_wait1(){ asm volatile("cp.async.wait_group 1;" ::: "memory"); }
__device__ __forceinline__ void cp_wait0(){ asm volatile("cp.async.wait_group 0;" ::: "memory"); }

// tf32 m16n8k8 mma: D += A*B  (A row-major 16x8, B col-major 8x8)
__device__ __forceinline__ void mma8(float* d, const float* a, float b0, float b1){
    asm volatile("mma.sync.aligned.m16n8k8.row.col.f32.tf32.tf32.f32 "
        "{%0,%1,%2,%3}, {%4,%5,%6,%7}, {%8,%9}, {%0,%1,%2,%3};"
        : "+f"(d[0]), "+f"(d[1]), "+f"(d[2]), "+f"(d[3])
        : "r"(__float_as_uint(a[0])), "r"(__float_as_uint(a[1])),
          "r"(__float_as_uint(a[2])), "r"(__float_as_uint(a[3])),
          "r"(__float_as_uint(b0)),  "r"(__float_as_uint(b1)));
}

// window-order row t <-> original-order row (self-inverse map)
__device__ __forceinline__ int winrow_to_orig(int t) {
    int b   = t / 3136;
    int rem = t - b * 3136;
    int w   = rem / 49;
    int n   = rem - w * 49;
    int wr = w >> 3, wc = w & 7;
    int r  = n / 7,  c  = n - r * 7;
    int gh = wr * 7 + r + 3; if (gh >= 56) gh -= 56;
    int gw = wc * 7 + c + 3; if (gw >= 56) gw -= 56;
    return b * 3136 + gh * 56 + gw;
}

// ---------------- LayerNorm (outputs TF32-rounded; optional window gather) --
template<int GATHER>
__global__ void __launch_bounds__(128) ln_kernel(
    const float* __restrict__ x, const float* __restrict__ g,
    const float* __restrict__ b, float* __restrict__ out)
{
    int t   = blockIdx.x;
    int src = GATHER ? winrow_to_orig(t) : t;
    const float* xr = x + (size_t)src * CDIM;
    int tid = threadIdx.x;

    float v0 = xr[tid], v1 = xr[tid + 128], v2 = xr[tid + 256];
    float s  = v0 + v1 + v2;
    float sq = v0 * v0 + v1 * v1 + v2 * v2;

    __shared__ float rs[128], rq[128];
    rs[tid] = s; rq[tid] = sq;
    __syncthreads();
    #pragma unroll
    for (int off = 64; off > 0; off >>= 1) {
        if (tid < off) { rs[tid] += rs[tid + off]; rq[tid] += rq[tid + off]; }
        __syncthreads();
    }
    float mean = rs[0] * (1.0f / CDIM);
    float var  = rq[0] * (1.0f / CDIM) - mean * mean;
    float inv  = rsqrtf(var + EPS);

    float* orow = out + (size_t)t * CDIM;
    orow[tid      ] = tf32r((v0 - mean) * inv * g[tid      ] + b[tid      ]);
    orow[tid + 128] = tf32r((v1 - mean) * inv * g[tid + 128] + b[tid + 128]);
    orow[tid + 256] = tf32r((v2 - mean) * inv * g[tid + 256] + b[tid + 256]);
}

// ---------------- weight transpose + TF32 round:  in[K,N] -> out[N,K] ------
__global__ void __launch_bounds__(256) transpose_round(
    const float* __restrict__ in, float* __restrict__ out, int K, int N)
{
    __shared__ float tile[32][33];
    int k0 = blockIdx.y * 32, n0 = blockIdx.x * 32;
    int tx = threadIdx.x, ty = threadIdx.y;
    #pragma unroll
    for (int i = ty; i < 32; i += 8)
        tile[i][tx] = in[(size_t)(k0 + i) * N + n0 + tx];
    __syncthreads();
    #pragma unroll
    for (int i = ty; i < 32; i += 8)
        out[(size_t)(n0 + i) * K + k0 + tx] = tf32r(tile[tx][i]);
}

// ---------------- TF32 mma.sync GEMM, 128x128 tile, K staged by 32 ---------
// 3-stage cp.async pipeline, one __syncthreads per stage.
// A: [M,K] row-major (tf32-rounded), Bt: [N,K] row-major (tf32-rounded)
// MODE 0: C = A*Bt' + bias
// MODE 1: C = tf32r(gelu(A*Bt' + bias))
// MODE 2: C = A*Bt' + bias + res
// MODE 3: C[map(row)] = A*Bt' + bias + res[map(row)]
#define STG_F   9216     // floats per stage ((128+128) * 36)
#define SMEM_SZ 110592   // 3 stages

template<int MODE>
__global__ void __launch_bounds__(256, 2) tc_gemm(
    const float* __restrict__ A, const float* __restrict__ Bt,
    const float* __restrict__ bias, const float* __restrict__ res,
    float* __restrict__ C, int N, int K)
{
    extern __shared__ float smem[];
    int tid  = threadIdx.x;
    int lane = tid & 31;
    int wid  = tid >> 5;
    int warp_m = wid & 1;          // 2 x 64 rows
    int warp_n = wid >> 1;         // 4 x 32 cols
    int m0 = blockIdx.y << 7, n0 = blockIdx.x << 7;

    const float* Arow = A  + (size_t)m0 * K;
    const float* Brow = Bt + (size_t)n0 * K;
    const int nst = K >> 5;

    uint32_t sbase = smem_u32(smem);

    int ldrow = tid >> 3;          // 0..31
    int ldc4  = tid & 7;           // 16B chunk within 32-float row

    auto issue_stage = [&](int s, int buf) {
        int kt = s << 5;
        uint32_t bA = sbase + (uint32_t)buf * (STG_F * 4);
        uint32_t bB = bA + 4608 * 4;
        #pragma unroll
        for (int p = 0; p < 4; ++p) {
            int row = ldrow + (p << 5);
            uint32_t doff = (uint32_t)row * 144 + (uint32_t)(ldc4 << 4);
            cp16(bA + doff, Arow + (size_t)row * K + kt + (ldc4 << 2));
            cp16(bB + doff, Brow + (size_t)row * K + kt + (ldc4 << 2));
        }
        cp_commit();
    };

    float acc[4][4][4];
    #pragma unroll
    for (int i = 0; i < 4; i++)
        #pragma unroll
        for (int j = 0; j < 4; j++)
            #pragma unroll
            for (int r = 0; r < 4; r++) acc[i][j][r] = 0.0f;

    issue_stage(0, 0);
    issue_stage(1, 1);

    int lr = lane >> 2;            // 0..7
    int lc = lane & 3;             // 0..3

    for (int s = 0; s < nst; ++s) {
        int buf = s % 3;
        if (s == nst - 1) cp_wait0(); else cp_wait1();
        __syncthreads();           // stage s visible; all threads done with s-1
        if (s + 2 < nst) issue_stage(s + 2, (s + 2) % 3);

        const float* As = smem + buf * STG_F;
        const float* Bs = As + 4608;

        #pragma unroll
        for (int kk = 0; kk < 32; kk += 8) {
            float a[4][4];
            #pragma unroll
            for (int mt = 0; mt < 4; mt++) {
                int r = (warp_m << 6) + (mt << 4) + lr;
                a[mt][0] = As[r * 36 + kk + lc];
                a[mt][1] = As[(r + 8) * 36 + kk + lc];
                a[mt][2] = As[r * 36 + kk + 4 + lc];
                a[mt][3] = As[(r + 8) * 36 + kk + 4 + lc];
            }
            #pragma unroll
            for (int nt = 0; nt < 4; nt++) {
                int c = (warp_n << 5) + (nt << 3) + lr;
                float b0 = Bs[c * 36 + kk + lc];
                float b1 = Bs[c * 36 + kk + 4 + lc];
                #pragma unroll
                for (int mt = 0; mt < 4; mt++)
                    mma8(acc[mt][nt], a[mt], b0, b1);
            }
        }
    }

    // ---- epilogue ----
    #pragma unroll
    for (int mt = 0; mt < 4; mt++) {
        #pragma unroll
        for (int h = 0; h < 2; h++) {
            int row  = m0 + (warp_m << 6) + (mt << 4) + lr + (h << 3);
            int orow = (MODE == 3) ? winrow_to_orig(row) : row;
            float* dst = C + (size_t)orow * N + n0 + (warp_n << 5);
            const float* rp = (MODE >= 2) ? (res + (size_t)orow * N + n0 + (warp_n << 5))
                                          : (const float*)0;
            #pragma unroll
            for (int nt = 0; nt < 4; nt++) {
                int c = (nt << 3) + (lc << 1);
                float2 bv = *(const float2*)(bias + n0 + (warp_n << 5) + c);
                float v0 = acc[mt][nt][h * 2 + 0] + bv.x;
                float v1 = acc[mt][nt][h * 2 + 1] + bv.y;
                if (MODE == 1) {
                    v0 = tf32r(0.5f * v0 * (1.0f + erff(v0 * 0.70710678118654752f)));
                    v1 = tf32r(0.5f * v1 * (1.0f + erff(v1 * 0.70710678118654752f)));
                } else if (MODE >= 2) {
                    float2 rv = *(const float2*)(rp + c);
                    v0 += rv.x; v1 += rv.y;
                }
                float2 o; o.x = v0; o.y = v1;
                *(float2*)(dst + c) = o;
            }
        }
    }
}

// ---------------- attention: one block per (window, head), conflict-free ---
__device__ __forceinline__ int regio(int g) { return g < 49 ? 0 : (g < 53 ? 1 : 2); }

__global__ void __launch_bounds__(256) attn_kernel(
    const float* __restrict__ qkv, const float* __restrict__ bias_table,
    float* __restrict__ o)
{
    int bh   = blockIdx.x;
    int wi   = bh / NHEAD;
    int head = bh - wi * NHEAD;
    int w    = wi & 63;
    int tid  = threadIdx.x;
    int lane = tid & 31;
    int wid  = tid >> 5;

    __shared__ float qs[49][36];
    __shared__ float ks[49][36];
    __shared__ float vs[49][36];
    __shared__ float S [49][49];

    size_t base = (size_t)wi * 49 * 1152 + head * 32;
    for (int e = tid; e < 49 * 32; e += 256) {
        int n = e >> 5, d = e & 31;
        size_t off = base + (size_t)n * 1152 + d;
        qs[n][d] = qkv[off] * SCALE;
        ks[n][d] = qkv[off + 384];
        vs[n][d] = qkv[off + 768];
    }
    __syncthreads();

    int wr = w >> 3, wc = w & 7;

    for (int i = wid; i < 49; i += 8) {
        float4 q[8];
        #pragma unroll
        for (int t = 0; t < 8; t++) q[t] = *(const float4*)&qs[i][t * 4];
        int ih = i / 7, iw = i - ih * 7;
        int li = regio(wr * 7 + ih) * 3 + regio(wc * 7 + iw);

        float sv0, sv1;
        {
            int j = lane;
            float s = 0.0f;
            #pragma unroll
            for (int t = 0; t < 8; t++) {
                float4 kv = *(const float4*)&ks[j][t * 4];
                s += q[t].x * kv.x + q[t].y * kv.y + q[t].z * kv.z + q[t].w * kv.w;
            }
            int jh = j / 7, jw = j - jh * 7;
            s += bias_table[((ih - jh + 6) * 13 + (iw - jw + 6)) * NHEAD + head];
            int lj = regio(wr * 7 + jh) * 3 + regio(wc * 7 + jw);
            if (li != lj) s -= 100.0f;
            sv0 = s;
        }
        if (lane < 17) {
            int j = lane + 32;
            float s = 0.0f;
            #pragma unroll
            for (int t = 0; t < 8; t++) {
                float4 kv = *(const float4*)&ks[j][t * 4];
                s += q[t].x * kv.x + q[t].y * kv.y + q[t].z * kv.z + q[t].w * kv.w;
            }
            int jh = j / 7, jw = j - jh * 7;
            s += bias_table[((ih - jh + 6) * 13 + (iw - jw + 6)) * NHEAD + head];
            int lj = regio(wr * 7 + jh) * 3 + regio(wc * 7 + jw);
            if (li != lj) s -= 100.0f;
            sv1 = s;
        } else sv1 = -1e30f;

        float mx = fmaxf(sv0, sv1);
        #pragma unroll
        for (int off = 16; off; off >>= 1) mx = fmaxf(mx, __shfl_xor_sync(~0u, mx, off));
        float e0 = __expf(sv0 - mx);
        float e1 = (lane < 17) ? __expf(sv1 - mx) : 0.0f;
        float sm = e0 + e1;
        #pragma unroll
        for (int off = 16; off; off >>= 1) sm += __shfl_xor_sync(~0u, sm, off);
        float inv = 1.0f / sm;
        S[i][lane] = e0 * inv;
        if (lane < 17) S[i][lane + 32] = e1 * inv;
    }
    __syncthreads();

    size_t obase = (size_t)wi * 49 * 384 + head * 32;
    for (int task = tid; task < 49 * 8; task += 256) {
        int i = task >> 3, d4 = task & 7;
        float ax = 0.f, ay = 0.f, az = 0.f, aw = 0.f;
        #pragma unroll 7
        for (int j = 0; j < 49; j++) {
            float s = S[i][j];
            float4 v = *(const float4*)&vs[j][d4 * 4];
            ax += s * v.x; ay += s * v.y; az += s * v.z; aw += s * v.w;
        }
        float4 r;
        r.x = tf32r(ax); r.y = tf32r(ay); r.z = tf32r(az); r.w = tf32r(aw);
        *(float4*)&o[obase + (size_t)i * 384 + d4 * 4] = r;
    }
}

// ---------------- host launch ----------------------------------------------
extern "C" void kernel_launch(void* const* d_in, const int* in_sizes, int n_in,
                              void* d_out, int out_size)
{
    const float* x       = (const float*)d_in[0];
    const float* ln1_g   = (const float*)d_in[1];
    const float* ln1_b   = (const float*)d_in[2];
    const float* qkv_w   = (const float*)d_in[3];
    const float* qkv_b   = (const float*)d_in[4];
    const float* proj_w  = (const float*)d_in[5];
    const float* proj_b  = (const float*)d_in[6];
    const float* bias_tb = (const float*)d_in[7];
    const float* ln2_g   = (const float*)d_in[8];
    const float* ln2_b   = (const float*)d_in[9];
    const float* fc1_w   = (const float*)d_in[10];
    const float* fc1_b   = (const float*)d_in[11];
    const float* fc2_w   = (const float*)d_in[12];
    const float* fc2_b   = (const float*)d_in[13];
    float*       out     = (float*)d_out;

    float *ph, *pqkv, *po, *pxa, *py, *pu, *pwt;
    cudaGetSymbolAddress((void**)&ph,   g_h);
    cudaGetSymbolAddress((void**)&pqkv, g_qkv);
    cudaGetSymbolAddress((void**)&po,   g_o);
    cudaGetSymbolAddress((void**)&pxa,  g_xa);
    cudaGetSymbolAddress((void**)&py,   g_y);
    cudaGetSymbolAddress((void**)&pu,   g_u);
    cudaGetSymbolAddress((void**)&pwt,  g_wt);

    cudaFuncSetAttribute(tc_gemm<0>, cudaFuncAttributeMaxDynamicSharedMemorySize, SMEM_SZ);
    cudaFuncSetAttribute(tc_gemm<1>, cudaFuncAttributeMaxDynamicSharedMemorySize, SMEM_SZ);
    cudaFuncSetAttribute(tc_gemm<2>, cudaFuncAttributeMaxDynamicSharedMemorySize, SMEM_SZ);
    cudaFuncSetAttribute(tc_gemm<3>, cudaFuncAttributeMaxDynamicSharedMemorySize, SMEM_SZ);

    // 0. weight transpose + tf32 round
    dim3 tb(32, 8);
    transpose_round<<<dim3(1152 / 32,  384 / 32), tb>>>(qkv_w,  pwt + WT_QKV,  384, 1152);
    transpose_round<<<dim3( 384 / 32,  384 / 32), tb>>>(proj_w, pwt + WT_PROJ, 384,  384);
    transpose_round<<<dim3(1536 / 32,  384 / 32), tb>>>(fc1_w,  pwt + WT_FC1,  384, 1536);
    transpose_round<<<dim3( 384 / 32, 1536 / 32), tb>>>(fc2_w,  pwt + WT_FC2, 1536,  384);

    // 1. LN1 + shift + window gather (tf32-rounded)
    ln_kernel<1><<<TOK, 128>>>(x, ln1_g, ln1_b, ph);

    // 2. qkv GEMM [100352 x 1152], K=384
    tc_gemm<0><<<dim3(9, TOK / 128), 256, SMEM_SZ>>>(ph, pwt + WT_QKV, qkv_b, nullptr, pqkv, 1152, 384);

    // 3. windowed attention (output tf32-rounded)
    attn_kernel<<<2048 * NHEAD, 256>>>(pqkv, bias_tb, po);

    // 4. proj GEMM + window-reverse scatter + residual(x)
    tc_gemm<3><<<dim3(3, TOK / 128), 256, SMEM_SZ>>>(po, pwt + WT_PROJ, proj_b, x, pxa, 384, 384);

    // 5. LN2 (tf32-rounded)
    ln_kernel<0><<<TOK, 128>>>(pxa, ln2_g, ln2_b, py);

    // 6. fc1 GEMM + gelu (tf32-rounded), N=1536
    tc_gemm<1><<<dim3(12, TOK / 128), 256, SMEM_SZ>>>(py, pwt + WT_FC1, fc1_b, nullptr, pu, 1536, 384);

    // 7. fc2 GEMM + residual -> out, K=1536
    tc_gemm<2><<<dim3(3, TOK / 128), 256, SMEM_SZ>>>(pu, pwt + WT_FC2, fc2_b, pxa, out, 384, 1536);
}

// round 7
// speedup vs baseline: 1.0234x; 1.0234x over previous
#include <cuda_runtime.h>
#include <math.h>
#include <stdint.h>

// ---------------- problem constants ----------------
#define CDIM    384
#define NHEAD   12
#define TOK     100352        // 32*3136
#define EPS     1e-5f
#define SCALE   0.17677669529663687f  // 1/sqrt(32)

// ---------------- scratch (device globals; no allocations) ----------------
__device__ float g_h  [(size_t)TOK * 384];
__device__ float g_qkv[(size_t)TOK * 1152];
__device__ float g_o  [(size_t)TOK * 384];
__device__ float g_xa [(size_t)TOK * 384];
__device__ float g_y  [(size_t)TOK * 384];
__device__ float g_u  [(size_t)TOK * 1536];
__device__ float g_wt [1769472];              // transposed+rounded weights

#define WT_QKV 0
#define WT_PROJ 442368
#define WT_FC1 589824
#define WT_FC2 1179648

// ---------------- small PTX helpers ----------------
__device__ __forceinline__ uint32_t smem_u32(const void* p){
    uint32_t a;
    asm("{ .reg .u64 t; cvta.to.shared.u64 t, %1; cvt.u32.u64 %0, t; }" : "=r"(a) : "l"(p));
    return a;
}
__device__ __forceinline__ float tf32r(float f){
    uint32_t r; asm("cvt.rna.tf32.f32 %0, %1;" : "=r"(r) : "f"(f));
    return __uint_as_float(r);
}
__device__ __forceinline__ void cp16(uint32_t d, const void* s){
    asm volatile("cp.async.cg.shared.global [%0], [%1], 16;" :: "r"(d), "l"(s));
}
__device__ __forceinline__ void cp_commit(){ asm volatile("cp.async.commit_group;"); }
__device__ __forceinline__ void cp_wait1(){ asm volatile("cp.async.wait_group 1;" ::: "memory"); }
__device__ __forceinline__ void cp_wait0(){ asm volatile("cp.async.wait_group 0;" ::: "memory"); }

// tf32 m16n8k8 mma: D += A*B  (A row-major 16x8, B col-major 8x8)
__device__ __forceinline__ void mma8(float* d, const float* a, float b0, float b1){
    asm volatile("mma.sync.aligned.m16n8k8.row.col.f32.tf32.tf32.f32 "
        "{%0,%1,%2,%3}, {%4,%5,%6,%7}, {%8,%9}, {%0,%1,%2,%3};"
        : "+f"(d[0]), "+f"(d[1]), "+f"(d[2]), "+f"(d[3])
        : "r"(__float_as_uint(a[0])), "r"(__float_as_uint(a[1])),
          "r"(__float_as_uint(a[2])), "r"(__float_as_uint(a[3])),
          "r"(__float_as_uint(b0)),  "r"(__float_as_uint(b1)));
}

// window-order row t <-> original-order row (self-inverse map)
__device__ __forceinline__ int winrow_to_orig(int t) {
    int b   = t / 3136;
    int rem = t - b * 3136;
    int w   = rem / 49;
    int n   = rem - w * 49;
    int wr = w >> 3, wc = w & 7;
    int r  = n / 7,  c  = n - r * 7;
    int gh = wr * 7 + r + 3; if (gh >= 56) gh -= 56;
    int gw = wc * 7 + c + 3; if (gw >= 56) gw -= 56;
    return b * 3136 + gh * 56 + gw;
}

// ---------------- LayerNorm (outputs TF32-rounded; optional window gather) --
template<int GATHER>
__global__ void __launch_bounds__(128) ln_kernel(
    const float* __restrict__ x, const float* __restrict__ g,
    const float* __restrict__ b, float* __restrict__ out)
{
    int t   = blockIdx.x;
    int src = GATHER ? winrow_to_orig(t) : t;
    const float* xr = x + (size_t)src * CDIM;
    int tid = threadIdx.x;

    float v0 = xr[tid], v1 = xr[tid + 128], v2 = xr[tid + 256];
    float s  = v0 + v1 + v2;
    float sq = v0 * v0 + v1 * v1 + v2 * v2;

    __shared__ float rs[128], rq[128];
    rs[tid] = s; rq[tid] = sq;
    __syncthreads();
    #pragma unroll
    for (int off = 64; off > 0; off >>= 1) {
        if (tid < off) { rs[tid] += rs[tid + off]; rq[tid] += rq[tid + off]; }
        __syncthreads();
    }
    float mean = rs[0] * (1.0f / CDIM);
    float var  = rq[0] * (1.0f / CDIM) - mean * mean;
    float inv  = rsqrtf(var + EPS);

    float* orow = out + (size_t)t * CDIM;
    orow[tid      ] = tf32r((v0 - mean) * inv * g[tid      ] + b[tid      ]);
    orow[tid + 128] = tf32r((v1 - mean) * inv * g[tid + 128] + b[tid + 128]);
    orow[tid + 256] = tf32r((v2 - mean) * inv * g[tid + 256] + b[tid + 256]);
}

// ---------------- weight transpose + TF32 round:  in[K,N] -> out[N,K] ------
__global__ void __launch_bounds__(256) transpose_round(
    const float* __restrict__ in, float* __restrict__ out, int K, int N)
{
    __shared__ float tile[32][33];
    int k0 = blockIdx.y * 32, n0 = blockIdx.x * 32;
    int tx = threadIdx.x, ty = threadIdx.y;
    #pragma unroll
    for (int i = ty; i < 32; i += 8)
        tile[i][tx] = in[(size_t)(k0 + i) * N + n0 + tx];
    __syncthreads();
    #pragma unroll
    for (int i = ty; i < 32; i += 8)
        out[(size_t)(n0 + i) * K + k0 + tx] = tf32r(tile[tx][i]);
}

// ---------------- TF32 mma.sync GEMM ---------------------------------------
// 128x128 CTA tile, 4 warps in 2x2 grid of 64x64 warp tiles, K staged by 32,
// 2-stage cp.async double buffer.
// A: [M,K] row-major (tf32-rounded), Bt: [N,K] row-major (tf32-rounded)
// MODE 0: C = A*Bt' + bias
// MODE 1: C = tf32r(gelu(A*Bt' + bias))
// MODE 2: C = A*Bt' + bias + res
// MODE 3: C[map(row)] = A*Bt' + bias + res[map(row)]
#define STG_F   9216     // floats per stage ((128+128) * 36)
#define SMEM_SZ 73728    // 2 stages

template<int MODE>
__global__ void __launch_bounds__(128, 2) tc_gemm(
    const float* __restrict__ A, const float* __restrict__ Bt,
    const float* __restrict__ bias, const float* __restrict__ res,
    float* __restrict__ C, int N, int K)
{
    extern __shared__ float smem[];
    int tid  = threadIdx.x;
    int lane = tid & 31;
    int wid  = tid >> 5;           // 0..3
    int warp_m = wid >> 1;         // 2 x 64 rows
    int warp_n = wid & 1;          // 2 x 64 cols
    int m0 = blockIdx.y << 7, n0 = blockIdx.x << 7;

    const float* Arow = A  + (size_t)m0 * K;
    const float* Brow = Bt + (size_t)n0 * K;
    const int nst = K >> 5;

    uint32_t sbase = smem_u32(smem);

    int ldrow = tid >> 3;          // 0..15
    int ldc4  = tid & 7;           // 16B chunk within 32-float row

    auto issue_stage = [&](int s, int buf) {
        int kt = s << 5;
        uint32_t bA = sbase + (uint32_t)buf * (STG_F * 4);
        uint32_t bB = bA + 4608 * 4;
        #pragma unroll
        for (int p = 0; p < 8; ++p) {
            int row = ldrow + (p << 4);
            uint32_t doff = (uint32_t)row * 144 + (uint32_t)(ldc4 << 4);
            cp16(bA + doff, Arow + (size_t)row * K + kt + (ldc4 << 2));
            cp16(bB + doff, Brow + (size_t)row * K + kt + (ldc4 << 2));
        }
        cp_commit();
    };

    float acc[4][8][4];
    #pragma unroll
    for (int i = 0; i < 4; i++)
        #pragma unroll
        for (int j = 0; j < 8; j++)
            #pragma unroll
            for (int r = 0; r < 4; r++) acc[i][j][r] = 0.0f;

    issue_stage(0, 0);

    int lr = lane >> 2;            // 0..7
    int lc = lane & 3;             // 0..3

    for (int s = 0; s < nst; ++s) {
        int buf = s & 1;
        __syncthreads();                        // prev compute done before overwrite
        if (s + 1 < nst) { issue_stage(s + 1, buf ^ 1); cp_wait1(); }
        else             { cp_wait0(); }
        __syncthreads();                        // stage s visible to all

        const float* As = smem + buf * STG_F;
        const float* Bs = As + 4608;

        #pragma unroll
        for (int kk = 0; kk < 32; kk += 8) {
            float a[4][4];
            #pragma unroll
            for (int mt = 0; mt < 4; mt++) {
                int r = (warp_m << 6) + (mt << 4) + lr;
                a[mt][0] = As[r * 36 + kk + lc];
                a[mt][1] = As[(r + 8) * 36 + kk + lc];
                a[mt][2] = As[r * 36 + kk + 4 + lc];
                a[mt][3] = As[(r + 8) * 36 + kk + 4 + lc];
            }
            #pragma unroll
            for (int nt = 0; nt < 8; nt++) {
                int c = (warp_n << 6) + (nt << 3) + lr;
                float b0 = Bs[c * 36 + kk + lc];
                float b1 = Bs[c * 36 + kk + 4 + lc];
                #pragma unroll
                for (int mt = 0; mt < 4; mt++)
                    mma8(acc[mt][nt], a[mt], b0, b1);
            }
        }
    }

    // ---- epilogue ----
    #pragma unroll
    for (int mt = 0; mt < 4; mt++) {
        #pragma unroll
        for (int h = 0; h < 2; h++) {
            int row  = m0 + (warp_m << 6) + (mt << 4) + lr + (h << 3);
            int orow = (MODE == 3) ? winrow_to_orig(row) : row;
            float* dst = C + (size_t)orow * N + n0 + (warp_n << 6);
            const float* rp = (MODE >= 2) ? (res + (size_t)orow * N + n0 + (warp_n << 6))
                                          : (const float*)0;
            #pragma unroll
            for (int nt = 0; nt < 8; nt++) {
                int c = (nt << 3) + (lc << 1);
                float2 bv = *(const float2*)(bias + n0 + (warp_n << 6) + c);
                float v0 = acc[mt][nt][h * 2 + 0] + bv.x;
                float v1 = acc[mt][nt][h * 2 + 1] + bv.y;
                if (MODE == 1) {
                    v0 = tf32r(0.5f * v0 * (1.0f + erff(v0 * 0.70710678118654752f)));
                    v1 = tf32r(0.5f * v1 * (1.0f + erff(v1 * 0.70710678118654752f)));
                } else if (MODE >= 2) {
                    float2 rv = *(const float2*)(rp + c);
                    v0 += rv.x; v1 += rv.y;
                }
                float2 o; o.x = v0; o.y = v1;
                *(float2*)(dst + c) = o;
            }
        }
    }
}

// ---------------- attention: one block per (window, head), conflict-free ---
__device__ __forceinline__ int regio(int g) { return g < 49 ? 0 : (g < 53 ? 1 : 2); }

__global__ void __launch_bounds__(256) attn_kernel(
    const float* __restrict__ qkv, const float* __restrict__ bias_table,
    float* __restrict__ o)
{
    int bh   = blockIdx.x;
    int wi   = bh / NHEAD;
    int head = bh - wi * NHEAD;
    int w    = wi & 63;
    int tid  = threadIdx.x;
    int lane = tid & 31;
    int wid  = tid >> 5;

    __shared__ float qs[49][36];
    __shared__ float ks[49][36];
    __shared__ float vs[49][36];
    __shared__ float S [49][49];

    size_t base = (size_t)wi * 49 * 1152 + head * 32;
    for (int e = tid; e < 49 * 32; e += 256) {
        int n = e >> 5, d = e & 31;
        size_t off = base + (size_t)n * 1152 + d;
        qs[n][d] = qkv[off] * SCALE;
        ks[n][d] = qkv[off + 384];
        vs[n][d] = qkv[off + 768];
    }
    __syncthreads();

    int wr = w >> 3, wc = w & 7;

    for (int i = wid; i < 49; i += 8) {
        float4 q[8];
        #pragma unroll
        for (int t = 0; t < 8; t++) q[t] = *(const float4*)&qs[i][t * 4];
        int ih = i / 7, iw = i - ih * 7;
        int li = regio(wr * 7 + ih) * 3 + regio(wc * 7 + iw);

        float sv0, sv1;
        {
            int j = lane;
            float s = 0.0f;
            #pragma unroll
            for (int t = 0; t < 8; t++) {
                float4 kv = *(const float4*)&ks[j][t * 4];
                s += q[t].x * kv.x + q[t].y * kv.y + q[t].z * kv.z + q[t].w * kv.w;
            }
            int jh = j / 7, jw = j - jh * 7;
            s += bias_table[((ih - jh + 6) * 13 + (iw - jw + 6)) * NHEAD + head];
            int lj = regio(wr * 7 + jh) * 3 + regio(wc * 7 + jw);
            if (li != lj) s -= 100.0f;
            sv0 = s;
        }
        if (lane < 17) {
            int j = lane + 32;
            float s = 0.0f;
            #pragma unroll
            for (int t = 0; t < 8; t++) {
                float4 kv = *(const float4*)&ks[j][t * 4];
                s += q[t].x * kv.x + q[t].y * kv.y + q[t].z * kv.z + q[t].w * kv.w;
            }
            int jh = j / 7, jw = j - jh * 7;
            s += bias_table[((ih - jh + 6) * 13 + (iw - jw + 6)) * NHEAD + head];
            int lj = regio(wr * 7 + jh) * 3 + regio(wc * 7 + jw);
            if (li != lj) s -= 100.0f;
            sv1 = s;
        } else sv1 = -1e30f;

        float mx = fmaxf(sv0, sv1);
        #pragma unroll
        for (int off = 16; off; off >>= 1) mx = fmaxf(mx, __shfl_xor_sync(~0u, mx, off));
        float e0 = __expf(sv0 - mx);
        float e1 = (lane < 17) ? __expf(sv1 - mx) : 0.0f;
        float sm = e0 + e1;
        #pragma unroll
        for (int off = 16; off; off >>= 1) sm += __shfl_xor_sync(~0u, sm, off);
        float inv = 1.0f / sm;
        S[i][lane] = e0 * inv;
        if (lane < 17) S[i][lane + 32] = e1 * inv;
    }
    __syncthreads();

    size_t obase = (size_t)wi * 49 * 384 + head * 32;
    for (int task = tid; task < 49 * 8; task += 256) {
        int i = task >> 3, d4 = task & 7;
        float ax = 0.f, ay = 0.f, az = 0.f, aw = 0.f;
        #pragma unroll 7
        for (int j = 0; j < 49; j++) {
            float s = S[i][j];
            float4 v = *(const float4*)&vs[j][d4 * 4];
            ax += s * v.x; ay += s * v.y; az += s * v.z; aw += s * v.w;
        }
        float4 r;
        r.x = tf32r(ax); r.y = tf32r(ay); r.z = tf32r(az); r.w = tf32r(aw);
        *(float4*)&o[obase + (size_t)i * 384 + d4 * 4] = r;
    }
}

// ---------------- host launch ----------------------------------------------
extern "C" void kernel_launch(void* const* d_in, const int* in_sizes, int n_in,
                              void* d_out, int out_size)
{
    const float* x       = (const float*)d_in[0];
    const float* ln1_g   = (const float*)d_in[1];
    const float* ln1_b   = (const float*)d_in[2];
    const float* qkv_w   = (const float*)d_in[3];
    const float* qkv_b   = (const float*)d_in[4];
    const float* proj_w  = (const float*)d_in[5];
    const float* proj_b  = (const float*)d_in[6];
    const float* bias_tb = (const float*)d_in[7];
    const float* ln2_g   = (const float*)d_in[8];
    const float* ln2_b   = (const float*)d_in[9];
    const float* fc1_w   = (const float*)d_in[10];
    const float* fc1_b   = (const float*)d_in[11];
    const float* fc2_w   = (const float*)d_in[12];
    const float* fc2_b   = (const float*)d_in[13];
    float*       out     = (float*)d_out;

    float *ph, *pqkv, *po, *pxa, *py, *pu, *pwt;
    cudaGetSymbolAddress((void**)&ph,   g_h);
    cudaGetSymbolAddress((void**)&pqkv, g_qkv);
    cudaGetSymbolAddress((void**)&po,   g_o);
    cudaGetSymbolAddress((void**)&pxa,  g_xa);
    cudaGetSymbolAddress((void**)&py,   g_y);
    cudaGetSymbolAddress((void**)&pu,   g_u);
    cudaGetSymbolAddress((void**)&pwt,  g_wt);

    cudaFuncSetAttribute(tc_gemm<0>, cudaFuncAttributeMaxDynamicSharedMemorySize, SMEM_SZ);
    cudaFuncSetAttribute(tc_gemm<1>, cudaFuncAttributeMaxDynamicSharedMemorySize, SMEM_SZ);
    cudaFuncSetAttribute(tc_gemm<2>, cudaFuncAttributeMaxDynamicSharedMemorySize, SMEM_SZ);
    cudaFuncSetAttribute(tc_gemm<3>, cudaFuncAttributeMaxDynamicSharedMemorySize, SMEM_SZ);

    // 0. weight transpose + tf32 round
    dim3 tb(32, 8);
    transpose_round<<<dim3(1152 / 32,  384 / 32), tb>>>(qkv_w,  pwt + WT_QKV,  384, 1152);
    transpose_round<<<dim3( 384 / 32,  384 / 32), tb>>>(proj_w, pwt + WT_PROJ, 384,  384);
    transpose_round<<<dim3(1536 / 32,  384 / 32), tb>>>(fc1_w,  pwt + WT_FC1,  384, 1536);
    transpose_round<<<dim3( 384 / 32, 1536 / 32), tb>>>(fc2_w,  pwt + WT_FC2, 1536,  384);

    // 1. LN1 + shift + window gather (tf32-rounded)
    ln_kernel<1><<<TOK, 128>>>(x, ln1_g, ln1_b, ph);

    // 2. qkv GEMM [100352 x 1152], K=384
    tc_gemm<0><<<dim3(9, TOK / 128), 128, SMEM_SZ>>>(ph, pwt + WT_QKV, qkv_b, nullptr, pqkv, 1152, 384);

    // 3. windowed attention (output tf32-rounded)
    attn_kernel<<<2048 * NHEAD, 256>>>(pqkv, bias_tb, po);

    // 4. proj GEMM + window-reverse scatter + residual(x)
    tc_gemm<3><<<dim3(3, TOK / 128), 128, SMEM_SZ>>>(po, pwt + WT_PROJ, proj_b, x, pxa, 384, 384);

    // 5. LN2 (tf32-rounded)
    ln_kernel<0><<<TOK, 128>>>(pxa, ln2_g, ln2_b, py);

    // 6. fc1 GEMM + gelu (tf32-rounded), N=1536
    tc_gemm<1><<<dim3(12, TOK / 128), 128, SMEM_SZ>>>(py, pwt + WT_FC1, fc1_b, nullptr, pu, 1536, 384);

    // 7. fc2 GEMM + residual -> out, K=1536
    tc_gemm<2><<<dim3(3, TOK / 128), 128, SMEM_SZ>>>(pu, pwt + WT_FC2, fc2_b, pxa, out, 384, 1536);
}

// round 8
// speedup vs baseline: 1.3488x; 1.3180x over previous
#include <cuda_runtime.h>
#include <cuda_fp16.h>
#include <math.h>
#include <stdint.h>

// ---------------- problem constants ----------------
#define CDIM    384
#define NHEAD   12
#define TOK     100352        // 32*3136
#define EPS     1e-5f
#define SCALE   0.17677669529663687f  // 1/sqrt(32)

// ---------------- scratch (device globals; no allocations) ----------------
__device__ __half g_h  [(size_t)TOK * 384];
__device__ __half g_qkv[(size_t)TOK * 1152];
__device__ __half g_o  [(size_t)TOK * 384];
__device__ float  g_xa [(size_t)TOK * 384];   // residual stream stays fp32
__device__ __half g_y  [(size_t)TOK * 384];
__device__ __half g_u  [(size_t)TOK * 1536];
__device__ __half g_wt [1769472];             // transposed fp16 weights

#define WT_QKV 0
#define WT_PROJ 442368
#define WT_FC1 589824
#define WT_FC2 1179648

// ---------------- small PTX helpers ----------------
__device__ __forceinline__ uint32_t smem_u32(const void* p){
    uint32_t a;
    asm("{ .reg .u64 t; cvta.to.shared.u64 t, %1; cvt.u32.u64 %0, t; }" : "=r"(a) : "l"(p));
    return a;
}
__device__ __forceinline__ void cp16(uint32_t d, const void* s){
    asm volatile("cp.async.cg.shared.global [%0], [%1], 16;" :: "r"(d), "l"(s));
}
__device__ __forceinline__ void cp_commit(){ asm volatile("cp.async.commit_group;"); }
__device__ __forceinline__ void cp_wait1(){ asm volatile("cp.async.wait_group 1;" ::: "memory"); }
__device__ __forceinline__ void cp_wait0(){ asm volatile("cp.async.wait_group 0;" ::: "memory"); }

// fp16 m16n8k16 mma, fp32 accumulate
__device__ __forceinline__ void mma16(float* d, uint32_t a0, uint32_t a1,
                                      uint32_t a2, uint32_t a3,
                                      uint32_t b0, uint32_t b1){
    asm volatile("mma.sync.aligned.m16n8k16.row.col.f32.f16.f16.f32 "
        "{%0,%1,%2,%3}, {%4,%5,%6,%7}, {%8,%9}, {%0,%1,%2,%3};"
        : "+f"(d[0]), "+f"(d[1]), "+f"(d[2]), "+f"(d[3])
        : "r"(a0), "r"(a1), "r"(a2), "r"(a3), "r"(b0), "r"(b1));
}

// window-order row t <-> original-order row (self-inverse map)
__device__ __forceinline__ int winrow_to_orig(int t) {
    int b   = t / 3136;
    int rem = t - b * 3136;
    int w   = rem / 49;
    int n   = rem - w * 49;
    int wr = w >> 3, wc = w & 7;
    int r  = n / 7,  c  = n - r * 7;
    int gh = wr * 7 + r + 3; if (gh >= 56) gh -= 56;
    int gw = wc * 7 + c + 3; if (gw >= 56) gw -= 56;
    return b * 3136 + gh * 56 + gw;
}

// ---------------- LayerNorm -> fp16 (optional window gather) ---------------
template<int GATHER>
__global__ void __launch_bounds__(128) ln_kernel(
    const float* __restrict__ x, const float* __restrict__ g,
    const float* __restrict__ b, __half* __restrict__ out)
{
    int t   = blockIdx.x;
    int src = GATHER ? winrow_to_orig(t) : t;
    const float* xr = x + (size_t)src * CDIM;
    int tid = threadIdx.x;

    float v0 = xr[tid], v1 = xr[tid + 128], v2 = xr[tid + 256];
    float s  = v0 + v1 + v2;
    float sq = v0 * v0 + v1 * v1 + v2 * v2;

    __shared__ float rs[128], rq[128];
    rs[tid] = s; rq[tid] = sq;
    __syncthreads();
    #pragma unroll
    for (int off = 64; off > 0; off >>= 1) {
        if (tid < off) { rs[tid] += rs[tid + off]; rq[tid] += rq[tid + off]; }
        __syncthreads();
    }
    float mean = rs[0] * (1.0f / CDIM);
    float var  = rq[0] * (1.0f / CDIM) - mean * mean;
    float inv  = rsqrtf(var + EPS);

    __half* orow = out + (size_t)t * CDIM;
    orow[tid      ] = __float2half((v0 - mean) * inv * g[tid      ] + b[tid      ]);
    orow[tid + 128] = __float2half((v1 - mean) * inv * g[tid + 128] + b[tid + 128]);
    orow[tid + 256] = __float2half((v2 - mean) * inv * g[tid + 256] + b[tid + 256]);
}

// ---------------- weight transpose + fp16 convert:  in[K,N] -> out[N,K] ----
__global__ void __launch_bounds__(256) transpose_half(
    const float* __restrict__ in, __half* __restrict__ out, int K, int N)
{
    __shared__ float tile[32][33];
    int k0 = blockIdx.y * 32, n0 = blockIdx.x * 32;
    int tx = threadIdx.x, ty = threadIdx.y;
    #pragma unroll
    for (int i = ty; i < 32; i += 8)
        tile[i][tx] = in[(size_t)(k0 + i) * N + n0 + tx];
    __syncthreads();
    #pragma unroll
    for (int i = ty; i < 32; i += 8)
        out[(size_t)(n0 + i) * K + k0 + tx] = __float2half(tile[tx][i]);
}

// ---------------- FP16 mma.sync GEMM ----------------------------------------
// 128x128 CTA tile, 4 warps in 2x2 grid of 64x64 warp tiles, K staged by 32,
// 2-stage cp.async double buffer. Rows padded to 40 halves (conflict-free).
// A: [M,K] fp16 row-major, Bt: [N,K] fp16 row-major
// MODE 0: Ch = A*Bt' + bias                 (fp16 out)
// MODE 1: Ch = gelu(A*Bt' + bias)           (fp16 out)
// MODE 2: Cf = A*Bt' + bias + res           (fp32 out)
// MODE 3: Cf[map(row)] = A*Bt' + bias + res[map(row)]  (fp32 out)
#define STG_B   20480    // bytes per stage: 2 matrices * 128 rows * 40 halves * 2B
#define SMEM_SZ 40960    // 2 stages

template<int MODE>
__global__ void __launch_bounds__(128, 2) tc_gemm(
    const __half* __restrict__ A, const __half* __restrict__ Bt,
    const float* __restrict__ bias, const float* __restrict__ res,
    void* __restrict__ Cv, int N, int K)
{
    extern __shared__ __align__(16) char smem[];
    int tid  = threadIdx.x;
    int lane = tid & 31;
    int wid  = tid >> 5;           // 0..3
    int warp_m = wid >> 1;         // 2 x 64 rows
    int warp_n = wid & 1;          // 2 x 64 cols
    int m0 = blockIdx.y << 7, n0 = blockIdx.x << 7;

    const __half* Arow = A  + (size_t)m0 * K;
    const __half* Brow = Bt + (size_t)n0 * K;
    const int nst = K >> 5;

    uint32_t sbase = smem_u32(smem);

    int ldrow = tid >> 2;          // 0..31 (p adds 32)
    int ldc   = tid & 3;           // 16B chunk (8 halves) within 32-half row

    auto issue_stage = [&](int s, int buf) {
        int kt = s << 5;
        uint32_t bA = sbase + (uint32_t)buf * STG_B;
        uint32_t bB = bA + 10240;
        #pragma unroll
        for (int p = 0; p < 4; ++p) {
            int row = ldrow + (p << 5);
            uint32_t doff = (uint32_t)row * 80 + (uint32_t)(ldc << 4);
            cp16(bA + doff, Arow + (size_t)row * K + kt + (ldc << 3));
            cp16(bB + doff, Brow + (size_t)row * K + kt + (ldc << 3));
        }
        cp_commit();
    };

    float acc[4][8][4];
    #pragma unroll
    for (int i = 0; i < 4; i++)
        #pragma unroll
        for (int j = 0; j < 8; j++)
            #pragma unroll
            for (int r = 0; r < 4; r++) acc[i][j][r] = 0.0f;

    issue_stage(0, 0);

    int lr = lane >> 2;            // 0..7
    int lc = lane & 3;             // 0..3

    for (int s = 0; s < nst; ++s) {
        int buf = s & 1;
        __syncthreads();                        // prev compute done before overwrite
        if (s + 1 < nst) { issue_stage(s + 1, buf ^ 1); cp_wait1(); }
        else             { cp_wait0(); }
        __syncthreads();                        // stage s visible to all

        const uint32_t* As32 = (const uint32_t*)(smem + buf * STG_B);
        const uint32_t* Bs32 = As32 + 2560;     // 5120 halves

        #pragma unroll
        for (int k2 = 0; k2 < 16; k2 += 8) {    // two k16 chunks (in half2 units)
            uint32_t a[4][4];
            #pragma unroll
            for (int mt = 0; mt < 4; mt++) {
                int base = ((warp_m << 6) + (mt << 4) + lr) * 20 + k2 + lc;
                a[mt][0] = As32[base];
                a[mt][1] = As32[base + 160];    // +8 rows
                a[mt][2] = As32[base + 4];      // +8 k
                a[mt][3] = As32[base + 164];
            }
            #pragma unroll
            for (int nt = 0; nt < 8; nt++) {
                int cbase = ((warp_n << 6) + (nt << 3) + lr) * 20 + k2 + lc;
                uint32_t b0 = Bs32[cbase];
                uint32_t b1 = Bs32[cbase + 4];
                #pragma unroll
                for (int mt = 0; mt < 4; mt++)
                    mma16(acc[mt][nt], a[mt][0], a[mt][1], a[mt][2], a[mt][3], b0, b1);
            }
        }
    }

    // ---- epilogue ----
    #pragma unroll
    for (int mt = 0; mt < 4; mt++) {
        #pragma unroll
        for (int h = 0; h < 2; h++) {
            int row  = m0 + (warp_m << 6) + (mt << 4) + lr + (h << 3);
            int orow = (MODE == 3) ? winrow_to_orig(row) : row;
            #pragma unroll
            for (int nt = 0; nt < 8; nt++) {
                int c = (warp_n << 6) + (nt << 3) + (lc << 1);
                float2 bv = *(const float2*)(bias + n0 + c);
                float v0 = acc[mt][nt][h * 2 + 0] + bv.x;
                float v1 = acc[mt][nt][h * 2 + 1] + bv.y;
                if (MODE == 1) {
                    v0 = 0.5f * v0 * (1.0f + erff(v0 * 0.70710678118654752f));
                    v1 = 0.5f * v1 * (1.0f + erff(v1 * 0.70710678118654752f));
                }
                if (MODE <= 1) {
                    __half2* dst = (__half2*)((__half*)Cv + (size_t)orow * N + n0 + c);
                    *dst = __floats2half2_rn(v0, v1);
                } else {
                    size_t cb = (size_t)orow * N + n0 + c;
                    float2 rv = *(const float2*)(res + cb);
                    float2 o; o.x = v0 + rv.x; o.y = v1 + rv.y;
                    *(float2*)((float*)Cv + cb) = o;
                }
            }
        }
    }
}

// ---------------- attention: one block per (window, head), conflict-free ---
__device__ __forceinline__ int regio(int g) { return g < 49 ? 0 : (g < 53 ? 1 : 2); }

__global__ void __launch_bounds__(256) attn_kernel(
    const __half* __restrict__ qkv, const float* __restrict__ bias_table,
    __half* __restrict__ o)
{
    int bh   = blockIdx.x;
    int wi   = bh / NHEAD;
    int head = bh - wi * NHEAD;
    int w    = wi & 63;
    int tid  = threadIdx.x;
    int lane = tid & 31;
    int wid  = tid >> 5;

    __shared__ float qs[49][36];
    __shared__ float ks[49][36];
    __shared__ float vs[49][36];
    __shared__ float S [49][49];

    size_t base = (size_t)wi * 49 * 1152 + head * 32;
    for (int e = tid; e < 49 * 32; e += 256) {
        int n = e >> 5, d = e & 31;
        size_t off = base + (size_t)n * 1152 + d;
        qs[n][d] = __half2float(qkv[off]) * SCALE;
        ks[n][d] = __half2float(qkv[off + 384]);
        vs[n][d] = __half2float(qkv[off + 768]);
    }
    __syncthreads();

    int wr = w >> 3, wc = w & 7;

    for (int i = wid; i < 49; i += 8) {
        float4 q[8];
        #pragma unroll
        for (int t = 0; t < 8; t++) q[t] = *(const float4*)&qs[i][t * 4];
        int ih = i / 7, iw = i - ih * 7;
        int li = regio(wr * 7 + ih) * 3 + regio(wc * 7 + iw);

        float sv0, sv1;
        {
            int j = lane;
            float s = 0.0f;
            #pragma unroll
            for (int t = 0; t < 8; t++) {
                float4 kv = *(const float4*)&ks[j][t * 4];
                s += q[t].x * kv.x + q[t].y * kv.y + q[t].z * kv.z + q[t].w * kv.w;
            }
            int jh = j / 7, jw = j - jh * 7;
            s += bias_table[((ih - jh + 6) * 13 + (iw - jw + 6)) * NHEAD + head];
            int lj = regio(wr * 7 + jh) * 3 + regio(wc * 7 + jw);
            if (li != lj) s -= 100.0f;
            sv0 = s;
        }
        if (lane < 17) {
            int j = lane + 32;
            float s = 0.0f;
            #pragma unroll
            for (int t = 0; t < 8; t++) {
                float4 kv = *(const float4*)&ks[j][t * 4];
                s += q[t].x * kv.x + q[t].y * kv.y + q[t].z * kv.z + q[t].w * kv.w;
            }
            int jh = j / 7, jw = j - jh * 7;
            s += bias_table[((ih - jh + 6) * 13 + (iw - jw + 6)) * NHEAD + head];
            int lj = regio(wr * 7 + jh) * 3 + regio(wc * 7 + jw);
            if (li != lj) s -= 100.0f;
            sv1 = s;
        } else sv1 = -1e30f;

        float mx = fmaxf(sv0, sv1);
        #pragma unroll
        for (int off = 16; off; off >>= 1) mx = fmaxf(mx, __shfl_xor_sync(~0u, mx, off));
        float e0 = __expf(sv0 - mx);
        float e1 = (lane < 17) ? __expf(sv1 - mx) : 0.0f;
        float sm = e0 + e1;
        #pragma unroll
        for (int off = 16; off; off >>= 1) sm += __shfl_xor_sync(~0u, sm, off);
        float inv = 1.0f / sm;
        S[i][lane] = e0 * inv;
        if (lane < 17) S[i][lane + 32] = e1 * inv;
    }
    __syncthreads();

    size_t obase = (size_t)wi * 49 * 384 + head * 32;
    for (int task = tid; task < 49 * 8; task += 256) {
        int i = task >> 3, d4 = task & 7;
        float ax = 0.f, ay = 0.f, az = 0.f, aw = 0.f;
        #pragma unroll 7
        for (int j = 0; j < 49; j++) {
            float s = S[i][j];
            float4 v = *(const float4*)&vs[j][d4 * 4];
            ax += s * v.x; ay += s * v.y; az += s * v.z; aw += s * v.w;
        }
        __half2* op = (__half2*)&o[obase + (size_t)i * 384 + d4 * 4];
        op[0] = __floats2half2_rn(ax, ay);
        op[1] = __floats2half2_rn(az, aw);
    }
}

// ---------------- host launch ----------------------------------------------
extern "C" void kernel_launch(void* const* d_in, const int* in_sizes, int n_in,
                              void* d_out, int out_size)
{
    const float* x       = (const float*)d_in[0];
    const float* ln1_g   = (const float*)d_in[1];
    const float* ln1_b   = (const float*)d_in[2];
    const float* qkv_w   = (const float*)d_in[3];
    const float* qkv_b   = (const float*)d_in[4];
    const float* proj_w  = (const float*)d_in[5];
    const float* proj_b  = (const float*)d_in[6];
    const float* bias_tb = (const float*)d_in[7];
    const float* ln2_g   = (const float*)d_in[8];
    const float* ln2_b   = (const float*)d_in[9];
    const float* fc1_w   = (const float*)d_in[10];
    const float* fc1_b   = (const float*)d_in[11];
    const float* fc2_w   = (const float*)d_in[12];
    const float* fc2_b   = (const float*)d_in[13];
    float*       out     = (float*)d_out;

    __half *ph, *pqkv, *po, *py, *pu, *pwt;
    float  *pxa;
    cudaGetSymbolAddress((void**)&ph,   g_h);
    cudaGetSymbolAddress((void**)&pqkv, g_qkv);
    cudaGetSymbolAddress((void**)&po,   g_o);
    cudaGetSymbolAddress((void**)&pxa,  g_xa);
    cudaGetSymbolAddress((void**)&py,   g_y);
    cudaGetSymbolAddress((void**)&pu,   g_u);
    cudaGetSymbolAddress((void**)&pwt,  g_wt);

    // 0. weight transpose + fp16 convert
    dim3 tb(32, 8);
    transpose_half<<<dim3(1152 / 32,  384 / 32), tb>>>(qkv_w,  pwt + WT_QKV,  384, 1152);
    transpose_half<<<dim3( 384 / 32,  384 / 32), tb>>>(proj_w, pwt + WT_PROJ, 384,  384);
    transpose_half<<<dim3(1536 / 32,  384 / 32), tb>>>(fc1_w,  pwt + WT_FC1,  384, 1536);
    transpose_half<<<dim3( 384 / 32, 1536 / 32), tb>>>(fc2_w,  pwt + WT_FC2, 1536,  384);

    // 1. LN1 + shift + window gather -> fp16
    ln_kernel<1><<<TOK, 128>>>(x, ln1_g, ln1_b, ph);

    // 2. qkv GEMM [100352 x 1152], K=384 -> fp16
    tc_gemm<0><<<dim3(9, TOK / 128), 128, SMEM_SZ>>>(ph, pwt + WT_QKV, qkv_b, nullptr, pqkv, 1152, 384);

    // 3. windowed attention -> fp16
    attn_kernel<<<2048 * NHEAD, 256>>>(pqkv, bias_tb, po);

    // 4. proj GEMM + window-reverse scatter + residual(x) -> fp32 xa
    tc_gemm<3><<<dim3(3, TOK / 128), 128, SMEM_SZ>>>(po, pwt + WT_PROJ, proj_b, x, pxa, 384, 384);

    // 5. LN2 -> fp16
    ln_kernel<0><<<TOK, 128>>>(pxa, ln2_g, ln2_b, py);

    // 6. fc1 GEMM + gelu, N=1536 -> fp16
    tc_gemm<1><<<dim3(12, TOK / 128), 128, SMEM_SZ>>>(py, pwt + WT_FC1, fc1_b, nullptr, pu, 1536, 384);

    // 7. fc2 GEMM + residual -> fp32 out, K=1536
    tc_gemm<2><<<dim3(3, TOK / 128), 128, SMEM_SZ>>>(pu, pwt + WT_FC2, fc2_b, pxa, out, 384, 1536);
}

// round 9
// speedup vs baseline: 1.3752x; 1.0195x over previous
#include <cuda_runtime.h>
#include <cuda_fp16.h>
#include <math.h>
#include <stdint.h>

// ---------------- problem constants ----------------
#define CDIM    384
#define NHEAD   12
#define TOK     100352        // 32*3136
#define EPS     1e-5f
#define SCALE   0.17677669529663687f  // 1/sqrt(32)

// ---------------- scratch (device globals; no allocations) ----------------
__device__ __half g_h  [(size_t)TOK * 384];
__device__ __half g_qkv[(size_t)TOK * 1152];
__device__ __half g_o  [(size_t)TOK * 384];
__device__ float  g_xa [(size_t)TOK * 384];   // residual stream stays fp32
__device__ __half g_y  [(size_t)TOK * 384];
__device__ __half g_u  [(size_t)TOK * 1536];
__device__ __half g_wt [1769472];             // transposed fp16 weights

#define WT_QKV 0
#define WT_PROJ 442368
#define WT_FC1 589824
#define WT_FC2 1179648

// ---------------- small PTX helpers ----------------
__device__ __forceinline__ uint32_t smem_u32(const void* p){
    uint32_t a;
    asm("{ .reg .u64 t; cvta.to.shared.u64 t, %1; cvt.u32.u64 %0, t; }" : "=r"(a) : "l"(p));
    return a;
}
__device__ __forceinline__ void cp16(uint32_t d, const void* s){
    asm volatile("cp.async.cg.shared.global [%0], [%1], 16;" :: "r"(d), "l"(s));
}
__device__ __forceinline__ void cp_commit(){ asm volatile("cp.async.commit_group;"); }
__device__ __forceinline__ void cp_wait1(){ asm volatile("cp.async.wait_group 1;" ::: "memory"); }
__device__ __forceinline__ void cp_wait0(){ asm volatile("cp.async.wait_group 0;" ::: "memory"); }

// fp16 m16n8k16 mma, fp32 accumulate
__device__ __forceinline__ void mma16(float* d, uint32_t a0, uint32_t a1,
                                      uint32_t a2, uint32_t a3,
                                      uint32_t b0, uint32_t b1){
    asm volatile("mma.sync.aligned.m16n8k16.row.col.f32.f16.f16.f32 "
        "{%0,%1,%2,%3}, {%4,%5,%6,%7}, {%8,%9}, {%0,%1,%2,%3};"
        : "+f"(d[0]), "+f"(d[1]), "+f"(d[2]), "+f"(d[3])
        : "r"(a0), "r"(a1), "r"(a2), "r"(a3), "r"(b0), "r"(b1));
}

__device__ __forceinline__ void ldsm4(uint32_t& r0, uint32_t& r1,
                                      uint32_t& r2, uint32_t& r3, uint32_t addr){
    asm volatile("ldmatrix.sync.aligned.m8n8.x4.shared.b16 {%0,%1,%2,%3}, [%4];"
        : "=r"(r0), "=r"(r1), "=r"(r2), "=r"(r3) : "r"(addr));
}

// window-order row t <-> original-order row (self-inverse map)
__device__ __forceinline__ int winrow_to_orig(int t) {
    int b   = t / 3136;
    int rem = t - b * 3136;
    int w   = rem / 49;
    int n   = rem - w * 49;
    int wr = w >> 3, wc = w & 7;
    int r  = n / 7,  c  = n - r * 7;
    int gh = wr * 7 + r + 3; if (gh >= 56) gh -= 56;
    int gw = wc * 7 + c + 3; if (gw >= 56) gw -= 56;
    return b * 3136 + gh * 56 + gw;
}

// ---------------- LayerNorm -> fp16 (optional window gather) ---------------
template<int GATHER>
__global__ void __launch_bounds__(128) ln_kernel(
    const float* __restrict__ x, const float* __restrict__ g,
    const float* __restrict__ b, __half* __restrict__ out)
{
    int t   = blockIdx.x;
    int src = GATHER ? winrow_to_orig(t) : t;
    const float* xr = x + (size_t)src * CDIM;
    int tid = threadIdx.x;

    float v0 = xr[tid], v1 = xr[tid + 128], v2 = xr[tid + 256];
    float s  = v0 + v1 + v2;
    float sq = v0 * v0 + v1 * v1 + v2 * v2;

    __shared__ float rs[128], rq[128];
    rs[tid] = s; rq[tid] = sq;
    __syncthreads();
    #pragma unroll
    for (int off = 64; off > 0; off >>= 1) {
        if (tid < off) { rs[tid] += rs[tid + off]; rq[tid] += rq[tid + off]; }
        __syncthreads();
    }
    float mean = rs[0] * (1.0f / CDIM);
    float var  = rq[0] * (1.0f / CDIM) - mean * mean;
    float inv  = rsqrtf(var + EPS);

    __half* orow = out + (size_t)t * CDIM;
    orow[tid      ] = __float2half((v0 - mean) * inv * g[tid      ] + b[tid      ]);
    orow[tid + 128] = __float2half((v1 - mean) * inv * g[tid + 128] + b[tid + 128]);
    orow[tid + 256] = __float2half((v2 - mean) * inv * g[tid + 256] + b[tid + 256]);
}

// ---------------- weight transpose + fp16 convert:  in[K,N] -> out[N,K] ----
__global__ void __launch_bounds__(256) transpose_half(
    const float* __restrict__ in, __half* __restrict__ out, int K, int N)
{
    __shared__ float tile[32][33];
    int k0 = blockIdx.y * 32, n0 = blockIdx.x * 32;
    int tx = threadIdx.x, ty = threadIdx.y;
    #pragma unroll
    for (int i = ty; i < 32; i += 8)
        tile[i][tx] = in[(size_t)(k0 + i) * N + n0 + tx];
    __syncthreads();
    #pragma unroll
    for (int i = ty; i < 32; i += 8)
        out[(size_t)(n0 + i) * K + k0 + tx] = __float2half(tile[tx][i]);
}

// ---------------- FP16 mma.sync GEMM ----------------------------------------
// 128x128 CTA tile, 8 warps in 2x4 grid of 64x32 warp tiles, K staged by 32,
// 2-stage cp.async double buffer, ldmatrix fragment loads.
// Rows padded to 40 halves (80 B) -> ldmatrix phases conflict-free.
// A: [M,K] fp16 row-major, Bt: [N,K] fp16 row-major
// MODE 0: Ch = A*Bt' + bias                 (fp16 out)
// MODE 1: Ch = gelu(A*Bt' + bias)           (fp16 out)
// MODE 2: Cf = A*Bt' + bias + res           (fp32 out)
// MODE 3: Cf[map(row)] = A*Bt' + bias + res[map(row)]  (fp32 out)
#define STG_B   20480    // bytes per stage: 2 matrices * 128 rows * 40 halves * 2B
#define SMEM_SZ 40960    // 2 stages

template<int MODE>
__global__ void __launch_bounds__(256, 2) tc_gemm(
    const __half* __restrict__ A, const __half* __restrict__ Bt,
    const float* __restrict__ bias, const float* __restrict__ res,
    void* __restrict__ Cv, int N, int K)
{
    extern __shared__ __align__(16) char smem[];
    int tid  = threadIdx.x;
    int lane = tid & 31;
    int wid  = tid >> 5;           // 0..7
    int warp_m = wid & 1;          // 2 x 64 rows
    int warp_n = wid >> 1;         // 4 x 32 cols
    int m0 = blockIdx.y << 7, n0 = blockIdx.x << 7;

    const __half* Arow = A  + (size_t)m0 * K;
    const __half* Brow = Bt + (size_t)n0 * K;
    const int nst = K >> 5;

    uint32_t sbase = smem_u32(smem);

    int ldrow = tid >> 2;          // 0..63 (p adds 64)
    int ldc   = tid & 3;           // 16B chunk (8 halves) within 32-half row

    auto issue_stage = [&](int s, int buf) {
        int kt = s << 5;
        uint32_t bA = sbase + (uint32_t)buf * STG_B;
        uint32_t bB = bA + 10240;
        #pragma unroll
        for (int p = 0; p < 2; ++p) {
            int row = ldrow + (p << 6);
            uint32_t doff = (uint32_t)row * 80 + (uint32_t)(ldc << 4);
            cp16(bA + doff, Arow + (size_t)row * K + kt + (ldc << 3));
            cp16(bB + doff, Brow + (size_t)row * K + kt + (ldc << 3));
        }
        cp_commit();
    };

    float acc[4][4][4];
    #pragma unroll
    for (int i = 0; i < 4; i++)
        #pragma unroll
        for (int j = 0; j < 4; j++)
            #pragma unroll
            for (int r = 0; r < 4; r++) acc[i][j][r] = 0.0f;

    issue_stage(0, 0);

    int lr = lane >> 2;            // 0..7
    int lc = lane & 3;             // 0..3

    // ldmatrix lane-address components
    uint32_t a_row = (uint32_t)((warp_m << 6) + (lane & 15));          // + mt*16
    uint32_t a_off = a_row * 80 + ((uint32_t)(lane >> 4) << 4);
    uint32_t b_row = (uint32_t)((warp_n << 5) + (lane & 7) + (((lane >> 4) & 1) << 3)); // + bt*16
    uint32_t b_off = b_row * 80 + (((uint32_t)(lane >> 3) & 1) << 4);

    for (int s = 0; s < nst; ++s) {
        int buf = s & 1;
        __syncthreads();                        // prev compute done before overwrite
        if (s + 1 < nst) { issue_stage(s + 1, buf ^ 1); cp_wait1(); }
        else             { cp_wait0(); }
        __syncthreads();                        // stage s visible to all

        uint32_t bA = sbase + (uint32_t)buf * STG_B;
        uint32_t bB = bA + 10240;

        #pragma unroll
        for (int kk = 0; kk < 2; kk++) {        // two k16 chunks, 32B apart
            uint32_t a[4][4];
            #pragma unroll
            for (int mt = 0; mt < 4; mt++)
                ldsm4(a[mt][0], a[mt][1], a[mt][2], a[mt][3],
                      bA + a_off + (uint32_t)(mt * 16 * 80) + (kk << 5));
            uint32_t b[2][4];
            #pragma unroll
            for (int bt = 0; bt < 2; bt++)
                ldsm4(b[bt][0], b[bt][1], b[bt][2], b[bt][3],
                      bB + b_off + (uint32_t)(bt * 16 * 80) + (kk << 5));
            #pragma unroll
            for (int mt = 0; mt < 4; mt++) {
                mma16(acc[mt][0], a[mt][0], a[mt][1], a[mt][2], a[mt][3], b[0][0], b[0][1]);
                mma16(acc[mt][1], a[mt][0], a[mt][1], a[mt][2], a[mt][3], b[0][2], b[0][3]);
                mma16(acc[mt][2], a[mt][0], a[mt][1], a[mt][2], a[mt][3], b[1][0], b[1][1]);
                mma16(acc[mt][3], a[mt][0], a[mt][1], a[mt][2], a[mt][3], b[1][2], b[1][3]);
            }
        }
    }

    // ---- epilogue ----
    #pragma unroll
    for (int mt = 0; mt < 4; mt++) {
        #pragma unroll
        for (int h = 0; h < 2; h++) {
            int row  = m0 + (warp_m << 6) + (mt << 4) + lr + (h << 3);
            int orow = (MODE == 3) ? winrow_to_orig(row) : row;
            #pragma unroll
            for (int nt = 0; nt < 4; nt++) {
                int c = (warp_n << 5) + (nt << 3) + (lc << 1);
                float2 bv = *(const float2*)(bias + n0 + c);
                float v0 = acc[mt][nt][h * 2 + 0] + bv.x;
                float v1 = acc[mt][nt][h * 2 + 1] + bv.y;
                if (MODE == 1) {
                    v0 = 0.5f * v0 * (1.0f + erff(v0 * 0.70710678118654752f));
                    v1 = 0.5f * v1 * (1.0f + erff(v1 * 0.70710678118654752f));
                }
                if (MODE <= 1) {
                    __half2* dst = (__half2*)((__half*)Cv + (size_t)orow * N + n0 + c);
                    *dst = __floats2half2_rn(v0, v1);
                } else {
                    size_t cb = (size_t)orow * N + n0 + c;
                    float2 rv = *(const float2*)(res + cb);
                    float2 o; o.x = v0 + rv.x; o.y = v1 + rv.y;
                    *(float2*)((float*)Cv + cb) = o;
                }
            }
        }
    }
}

// ---------------- attention: one block per (window, head), conflict-free ---
__device__ __forceinline__ int regio(int g) { return g < 49 ? 0 : (g < 53 ? 1 : 2); }

__global__ void __launch_bounds__(256) attn_kernel(
    const __half* __restrict__ qkv, const float* __restrict__ bias_table,
    __half* __restrict__ o)
{
    int bh   = blockIdx.x;
    int wi   = bh / NHEAD;
    int head = bh - wi * NHEAD;
    int w    = wi & 63;
    int tid  = threadIdx.x;
    int lane = tid & 31;
    int wid  = tid >> 5;

    __shared__ float qs[49][36];
    __shared__ float ks[49][36];
    __shared__ float vs[49][36];
    __shared__ float S [49][49];

    size_t base = (size_t)wi * 49 * 1152 + head * 32;
    for (int e = tid; e < 49 * 32; e += 256) {
        int n = e >> 5, d = e & 31;
        size_t off = base + (size_t)n * 1152 + d;
        qs[n][d] = __half2float(qkv[off]) * SCALE;
        ks[n][d] = __half2float(qkv[off + 384]);
        vs[n][d] = __half2float(qkv[off + 768]);
    }
    __syncthreads();

    int wr = w >> 3, wc = w & 7;

    for (int i = wid; i < 49; i += 8) {
        float4 q[8];
        #pragma unroll
        for (int t = 0; t < 8; t++) q[t] = *(const float4*)&qs[i][t * 4];
        int ih = i / 7, iw = i - ih * 7;
        int li = regio(wr * 7 + ih) * 3 + regio(wc * 7 + iw);

        float sv0, sv1;
        {
            int j = lane;
            float s = 0.0f;
            #pragma unroll
            for (int t = 0; t < 8; t++) {
                float4 kv = *(const float4*)&ks[j][t * 4];
                s += q[t].x * kv.x + q[t].y * kv.y + q[t].z * kv.z + q[t].w * kv.w;
            }
            int jh = j / 7, jw = j - jh * 7;
            s += bias_table[((ih - jh + 6) * 13 + (iw - jw + 6)) * NHEAD + head];
            int lj = regio(wr * 7 + jh) * 3 + regio(wc * 7 + jw);
            if (li != lj) s -= 100.0f;
            sv0 = s;
        }
        if (lane < 17) {
            int j = lane + 32;
            float s = 0.0f;
            #pragma unroll
            for (int t = 0; t < 8; t++) {
                float4 kv = *(const float4*)&ks[j][t * 4];
                s += q[t].x * kv.x + q[t].y * kv.y + q[t].z * kv.z + q[t].w * kv.w;
            }
            int jh = j / 7, jw = j - jh * 7;
            s += bias_table[((ih - jh + 6) * 13 + (iw - jw + 6)) * NHEAD + head];
            int lj = regio(wr * 7 + jh) * 3 + regio(wc * 7 + jw);
            if (li != lj) s -= 100.0f;
            sv1 = s;
        } else sv1 = -1e30f;

        float mx = fmaxf(sv0, sv1);
        #pragma unroll
        for (int off = 16; off; off >>= 1) mx = fmaxf(mx, __shfl_xor_sync(~0u, mx, off));
        float e0 = __expf(sv0 - mx);
        float e1 = (lane < 17) ? __expf(sv1 - mx) : 0.0f;
        float sm = e0 + e1;
        #pragma unroll
        for (int off = 16; off; off >>= 1) sm += __shfl_xor_sync(~0u, sm, off);
        float inv = 1.0f / sm;
        S[i][lane] = e0 * inv;
        if (lane < 17) S[i][lane + 32] = e1 * inv;
    }
    __syncthreads();

    size_t obase = (size_t)wi * 49 * 384 + head * 32;
    for (int task = tid; task < 49 * 8; task += 256) {
        int i = task >> 3, d4 = task & 7;
        float ax = 0.f, ay = 0.f, az = 0.f, aw = 0.f;
        #pragma unroll 7
        for (int j = 0; j < 49; j++) {
            float s = S[i][j];
            float4 v = *(const float4*)&vs[j][d4 * 4];
            ax += s * v.x; ay += s * v.y; az += s * v.z; aw += s * v.w;
        }
        __half2* op = (__half2*)&o[obase + (size_t)i * 384 + d4 * 4];
        op[0] = __floats2half2_rn(ax, ay);
        op[1] = __floats2half2_rn(az, aw);
    }
}

// ---------------- host launch ----------------------------------------------
extern "C" void kernel_launch(void* const* d_in, const int* in_sizes, int n_in,
                              void* d_out, int out_size)
{
    const float* x       = (const float*)d_in[0];
    const float* ln1_g   = (const float*)d_in[1];
    const float* ln1_b   = (const float*)d_in[2];
    const float* qkv_w   = (const float*)d_in[3];
    const float* qkv_b   = (const float*)d_in[4];
    const float* proj_w  = (const float*)d_in[5];
    const float* proj_b  = (const float*)d_in[6];
    const float* bias_tb = (const float*)d_in[7];
    const float* ln2_g   = (const float*)d_in[8];
    const float* ln2_b   = (const float*)d_in[9];
    const float* fc1_w   = (const float*)d_in[10];
    const float* fc1_b   = (const float*)d_in[11];
    const float* fc2_w   = (const float*)d_in[12];
    const float* fc2_b   = (const float*)d_in[13];
    float*       out     = (float*)d_out;

    __half *ph, *pqkv, *po, *py, *pu, *pwt;
    float  *pxa;
    cudaGetSymbolAddress((void**)&ph,   g_h);
    cudaGetSymbolAddress((void**)&pqkv, g_qkv);
    cudaGetSymbolAddress((void**)&po,   g_o);
    cudaGetSymbolAddress((void**)&pxa,  g_xa);
    cudaGetSymbolAddress((void**)&py,   g_y);
    cudaGetSymbolAddress((void**)&pu,   g_u);
    cudaGetSymbolAddress((void**)&pwt,  g_wt);

    // 0. weight transpose + fp16 convert
    dim3 tb(32, 8);
    transpose_half<<<dim3(1152 / 32,  384 / 32), tb>>>(qkv_w,  pwt + WT_QKV,  384, 1152);
    transpose_half<<<dim3( 384 / 32,  384 / 32), tb>>>(proj_w, pwt + WT_PROJ, 384,  384);
    transpose_half<<<dim3(1536 / 32,  384 / 32), tb>>>(fc1_w,  pwt + WT_FC1,  384, 1536);
    transpose_half<<<dim3( 384 / 32, 1536 / 32), tb>>>(fc2_w,  pwt + WT_FC2, 1536,  384);

    // 1. LN1 + shift + window gather -> fp16
    ln_kernel<1><<<TOK, 128>>>(x, ln1_g, ln1_b, ph);

    // 2. qkv GEMM [100352 x 1152], K=384 -> fp16
    tc_gemm<0><<<dim3(9, TOK / 128), 256, SMEM_SZ>>>(ph, pwt + WT_QKV, qkv_b, nullptr, pqkv, 1152, 384);

    // 3. windowed attention -> fp16
    attn_kernel<<<2048 * NHEAD, 256>>>(pqkv, bias_tb, po);

    // 4. proj GEMM + window-reverse scatter + residual(x) -> fp32 xa
    tc_gemm<3><<<dim3(3, TOK / 128), 256, SMEM_SZ>>>(po, pwt + WT_PROJ, proj_b, x, pxa, 384, 384);

    // 5. LN2 -> fp16
    ln_kernel<0><<<TOK, 128>>>(pxa, ln2_g, ln2_b, py);

    // 6. fc1 GEMM + gelu, N=1536 -> fp16
    tc_gemm<1><<<dim3(12, TOK / 128), 256, SMEM_SZ>>>(py, pwt + WT_FC1, fc1_b, nullptr, pu, 1536, 384);

    // 7. fc2 GEMM + residual -> fp32 out, K=1536
    tc_gemm<2><<<dim3(3, TOK / 128), 256, SMEM_SZ>>>(pu, pwt + WT_FC2, fc2_b, pxa, out, 384, 1536);
}

// round 10
// speedup vs baseline: 1.4452x; 1.0509x over previous
#include <cuda_runtime.h>
#include <cuda_fp16.h>
#include <math.h>
#include <stdint.h>

// ---------------- problem constants ----------------
#define CDIM    384
#define NHEAD   12
#define TOK     100352        // 32*3136
#define EPS     1e-5f
#define SCALE   0.17677669529663687f  // 1/sqrt(32)

// ---------------- scratch (device globals; no allocations) ----------------
__device__ __half g_h  [(size_t)TOK * 384];
__device__ __half g_qkv[(size_t)TOK * 1152];
__device__ __half g_o  [(size_t)TOK * 384];
__device__ float  g_xa [(size_t)TOK * 384];   // residual stream stays fp32
__device__ __half g_y  [(size_t)TOK * 384];
__device__ __half g_u  [(size_t)TOK * 1536];
__device__ __half g_wt [1769472];             // transposed fp16 weights

#define WT_QKV 0
#define WT_PROJ 442368
#define WT_FC1 589824
#define WT_FC2 1179648

// ---------------- small PTX helpers ----------------
__device__ __forceinline__ uint32_t smem_u32(const void* p){
    uint32_t a;
    asm("{ .reg .u64 t; cvta.to.shared.u64 t, %1; cvt.u32.u64 %0, t; }" : "=r"(a) : "l"(p));
    return a;
}
__device__ __forceinline__ void cp16(uint32_t d, const void* s){
    asm volatile("cp.async.cg.shared.global [%0], [%1], 16;" :: "r"(d), "l"(s));
}
__device__ __forceinline__ void cp_commit(){ asm volatile("cp.async.commit_group;"); }
__device__ __forceinline__ void cp_wait1(){ asm volatile("cp.async.wait_group 1;" ::: "memory"); }
__device__ __forceinline__ void cp_wait0(){ asm volatile("cp.async.wait_group 0;" ::: "memory"); }

// fp16 m16n8k16 mma, fp32 accumulate
__device__ __forceinline__ void mma16(float* d, uint32_t a0, uint32_t a1,
                                      uint32_t a2, uint32_t a3,
                                      uint32_t b0, uint32_t b1){
    asm volatile("mma.sync.aligned.m16n8k16.row.col.f32.f16.f16.f32 "
        "{%0,%1,%2,%3}, {%4,%5,%6,%7}, {%8,%9}, {%0,%1,%2,%3};"
        : "+f"(d[0]), "+f"(d[1]), "+f"(d[2]), "+f"(d[3])
        : "r"(a0), "r"(a1), "r"(a2), "r"(a3), "r"(b0), "r"(b1));
}

__device__ __forceinline__ void ldsm4(uint32_t& r0, uint32_t& r1,
                                      uint32_t& r2, uint32_t& r3, uint32_t addr){
    asm volatile("ldmatrix.sync.aligned.m8n8.x4.shared.b16 {%0,%1,%2,%3}, [%4];"
        : "=r"(r0), "=r"(r1), "=r"(r2), "=r"(r3) : "r"(addr));
}

// window-order row t <-> original-order row (self-inverse map)
__device__ __forceinline__ int winrow_to_orig(int t) {
    int b   = t / 3136;
    int rem = t - b * 3136;
    int w   = rem / 49;
    int n   = rem - w * 49;
    int wr = w >> 3, wc = w & 7;
    int r  = n / 7,  c  = n - r * 7;
    int gh = wr * 7 + r + 3; if (gh >= 56) gh -= 56;
    int gw = wc * 7 + c + 3; if (gw >= 56) gw -= 56;
    return b * 3136 + gh * 56 + gw;
}

// ---------------- LayerNorm -> fp16, warp-per-token, no smem/syncs ---------
template<int GATHER>
__global__ void __launch_bounds__(128) ln_kernel(
    const float* __restrict__ x, const float* __restrict__ g,
    const float* __restrict__ b, __half* __restrict__ out)
{
    int warp = threadIdx.x >> 5, lane = threadIdx.x & 31;
    int t    = (blockIdx.x << 2) + warp;
    int src  = GATHER ? winrow_to_orig(t) : t;

    const float4* xr = (const float4*)(x + (size_t)src * CDIM) + lane * 3;
    float4 v0 = xr[0], v1 = xr[1], v2 = xr[2];

    float s  = v0.x + v0.y + v0.z + v0.w + v1.x + v1.y + v1.z + v1.w
             + v2.x + v2.y + v2.z + v2.w;
    float sq = v0.x*v0.x + v0.y*v0.y + v0.z*v0.z + v0.w*v0.w
             + v1.x*v1.x + v1.y*v1.y + v1.z*v1.z + v1.w*v1.w
             + v2.x*v2.x + v2.y*v2.y + v2.z*v2.z + v2.w*v2.w;
    #pragma unroll
    for (int off = 16; off; off >>= 1) {
        s  += __shfl_xor_sync(~0u, s,  off);
        sq += __shfl_xor_sync(~0u, sq, off);
    }
    float mean = s * (1.0f / CDIM);
    float var  = sq * (1.0f / CDIM) - mean * mean;
    float inv  = rsqrtf(var + EPS);

    const float4* gp = (const float4*)g + lane * 3;
    const float4* bp = (const float4*)b + lane * 3;
    float4 g0 = gp[0], g1 = gp[1], g2 = gp[2];
    float4 b0 = bp[0], b1 = bp[1], b2 = bp[2];

    __half2* op = (__half2*)(out + (size_t)t * CDIM + lane * 12);
    op[0] = __floats2half2_rn((v0.x - mean) * inv * g0.x + b0.x, (v0.y - mean) * inv * g0.y + b0.y);
    op[1] = __floats2half2_rn((v0.z - mean) * inv * g0.z + b0.z, (v0.w - mean) * inv * g0.w + b0.w);
    op[2] = __floats2half2_rn((v1.x - mean) * inv * g1.x + b1.x, (v1.y - mean) * inv * g1.y + b1.y);
    op[3] = __floats2half2_rn((v1.z - mean) * inv * g1.z + b1.z, (v1.w - mean) * inv * g1.w + b1.w);
    op[4] = __floats2half2_rn((v2.x - mean) * inv * g2.x + b2.x, (v2.y - mean) * inv * g2.y + b2.y);
    op[5] = __floats2half2_rn((v2.z - mean) * inv * g2.z + b2.z, (v2.w - mean) * inv * g2.w + b2.w);
}

// ---------------- weight transpose + fp16 convert:  in[K,N] -> out[N,K] ----
__global__ void __launch_bounds__(256) transpose_half(
    const float* __restrict__ in, __half* __restrict__ out, int K, int N)
{
    __shared__ float tile[32][33];
    int k0 = blockIdx.y * 32, n0 = blockIdx.x * 32;
    int tx = threadIdx.x, ty = threadIdx.y;
    #pragma unroll
    for (int i = ty; i < 32; i += 8)
        tile[i][tx] = in[(size_t)(k0 + i) * N + n0 + tx];
    __syncthreads();
    #pragma unroll
    for (int i = ty; i < 32; i += 8)
        out[(size_t)(n0 + i) * K + k0 + tx] = __float2half(tile[tx][i]);
}

// ---------------- FP16 mma.sync GEMM ----------------------------------------
// 128x128 CTA tile, 8 warps in 2x4 grid of 64x32 warp tiles, K staged by 32,
// 2-stage cp.async double buffer, ldmatrix fragment loads.
// Rows padded to 40 halves (80 B) -> ldmatrix phases conflict-free.
// MODE 0: Ch = A*Bt' + bias                 (fp16 out)
// MODE 1: Ch = gelu(A*Bt' + bias)           (fp16 out)
// MODE 2: Cf = A*Bt' + bias + res           (fp32 out)
// MODE 3: Cf[map(row)] = A*Bt' + bias + res[map(row)]  (fp32 out)
#define STG_B   20480    // bytes per stage
#define SMEM_SZ 40960    // 2 stages

template<int MODE>
__global__ void __launch_bounds__(256, 2) tc_gemm(
    const __half* __restrict__ A, const __half* __restrict__ Bt,
    const float* __restrict__ bias, const float* __restrict__ res,
    void* __restrict__ Cv, int N, int K)
{
    extern __shared__ __align__(16) char smem[];
    int tid  = threadIdx.x;
    int lane = tid & 31;
    int wid  = tid >> 5;           // 0..7
    int warp_m = wid & 1;          // 2 x 64 rows
    int warp_n = wid >> 1;         // 4 x 32 cols
    int m0 = blockIdx.y << 7, n0 = blockIdx.x << 7;

    const __half* Arow = A  + (size_t)m0 * K;
    const __half* Brow = Bt + (size_t)n0 * K;
    const int nst = K >> 5;

    uint32_t sbase = smem_u32(smem);

    int ldrow = tid >> 2;          // 0..63 (p adds 64)
    int ldc   = tid & 3;           // 16B chunk (8 halves) within 32-half row

    auto issue_stage = [&](int s, int buf) {
        int kt = s << 5;
        uint32_t bA = sbase + (uint32_t)buf * STG_B;
        uint32_t bB = bA + 10240;
        #pragma unroll
        for (int p = 0; p < 2; ++p) {
            int row = ldrow + (p << 6);
            uint32_t doff = (uint32_t)row * 80 + (uint32_t)(ldc << 4);
            cp16(bA + doff, Arow + (size_t)row * K + kt + (ldc << 3));
            cp16(bB + doff, Brow + (size_t)row * K + kt + (ldc << 3));
        }
        cp_commit();
    };

    float acc[4][4][4];
    #pragma unroll
    for (int i = 0; i < 4; i++)
        #pragma unroll
        for (int j = 0; j < 4; j++)
            #pragma unroll
            for (int r = 0; r < 4; r++) acc[i][j][r] = 0.0f;

    issue_stage(0, 0);

    int lr = lane >> 2;            // 0..7
    int lc = lane & 3;             // 0..3

    uint32_t a_row = (uint32_t)((warp_m << 6) + (lane & 15));
    uint32_t a_off = a_row * 80 + ((uint32_t)(lane >> 4) << 4);
    uint32_t b_row = (uint32_t)((warp_n << 5) + (lane & 7) + (((lane >> 4) & 1) << 3));
    uint32_t b_off = b_row * 80 + (((uint32_t)(lane >> 3) & 1) << 4);

    for (int s = 0; s < nst; ++s) {
        int buf = s & 1;
        __syncthreads();
        if (s + 1 < nst) { issue_stage(s + 1, buf ^ 1); cp_wait1(); }
        else             { cp_wait0(); }
        __syncthreads();

        uint32_t bA = sbase + (uint32_t)buf * STG_B;
        uint32_t bB = bA + 10240;

        #pragma unroll
        for (int kk = 0; kk < 2; kk++) {
            uint32_t a[4][4];
            #pragma unroll
            for (int mt = 0; mt < 4; mt++)
                ldsm4(a[mt][0], a[mt][1], a[mt][2], a[mt][3],
                      bA + a_off + (uint32_t)(mt * 16 * 80) + (kk << 5));
            uint32_t b[2][4];
            #pragma unroll
            for (int bt = 0; bt < 2; bt++)
                ldsm4(b[bt][0], b[bt][1], b[bt][2], b[bt][3],
                      bB + b_off + (uint32_t)(bt * 16 * 80) + (kk << 5));
            #pragma unroll
            for (int mt = 0; mt < 4; mt++) {
                mma16(acc[mt][0], a[mt][0], a[mt][1], a[mt][2], a[mt][3], b[0][0], b[0][1]);
                mma16(acc[mt][1], a[mt][0], a[mt][1], a[mt][2], a[mt][3], b[0][2], b[0][3]);
                mma16(acc[mt][2], a[mt][0], a[mt][1], a[mt][2], a[mt][3], b[1][0], b[1][1]);
                mma16(acc[mt][3], a[mt][0], a[mt][1], a[mt][2], a[mt][3], b[1][2], b[1][3]);
            }
        }
    }

    // ---- epilogue ----
    #pragma unroll
    for (int mt = 0; mt < 4; mt++) {
        #pragma unroll
        for (int h = 0; h < 2; h++) {
            int row  = m0 + (warp_m << 6) + (mt << 4) + lr + (h << 3);
            int orow = (MODE == 3) ? winrow_to_orig(row) : row;
            #pragma unroll
            for (int nt = 0; nt < 4; nt++) {
                int c = (warp_n << 5) + (nt << 3) + (lc << 1);
                float2 bv = *(const float2*)(bias + n0 + c);
                float v0 = acc[mt][nt][h * 2 + 0] + bv.x;
                float v1 = acc[mt][nt][h * 2 + 1] + bv.y;
                if (MODE == 1) {
                    v0 = 0.5f * v0 * (1.0f + erff(v0 * 0.70710678118654752f));
                    v1 = 0.5f * v1 * (1.0f + erff(v1 * 0.70710678118654752f));
                }
                if (MODE <= 1) {
                    __half2* dst = (__half2*)((__half*)Cv + (size_t)orow * N + n0 + c);
                    *dst = __floats2half2_rn(v0, v1);
                } else {
                    size_t cb = (size_t)orow * N + n0 + c;
                    float2 rv = *(const float2*)(res + cb);
                    float2 o; o.x = v0 + rv.x; o.y = v1 + rv.y;
                    *(float2*)((float*)Cv + cb) = o;
                }
            }
        }
    }
}

// ---------------- attention: one block per (window, head), conflict-free ---
__device__ __forceinline__ int regio(int g) { return g < 49 ? 0 : (g < 53 ? 1 : 2); }

__global__ void __launch_bounds__(256) attn_kernel(
    const __half* __restrict__ qkv, const float* __restrict__ bias_table,
    __half* __restrict__ o)
{
    int bh   = blockIdx.x;
    int wi   = bh / NHEAD;
    int head = bh - wi * NHEAD;
    int w    = wi & 63;
    int tid  = threadIdx.x;
    int lane = tid & 31;
    int wid  = tid >> 5;

    __shared__ float qs[49][36];
    __shared__ float ks[49][36];
    __shared__ float vs[49][36];
    __shared__ float S [49][49];

    size_t base = (size_t)wi * 49 * 1152 + head * 32;
    for (int e = tid; e < 49 * 32; e += 256) {
        int n = e >> 5, d = e & 31;
        size_t off = base + (size_t)n * 1152 + d;
        qs[n][d] = __half2float(qkv[off]) * SCALE;
        ks[n][d] = __half2float(qkv[off + 384]);
        vs[n][d] = __half2float(qkv[off + 768]);
    }
    __syncthreads();

    int wr = w >> 3, wc = w & 7;

    for (int i = wid; i < 49; i += 8) {
        float4 q[8];
        #pragma unroll
        for (int t = 0; t < 8; t++) q[t] = *(const float4*)&qs[i][t * 4];
        int ih = i / 7, iw = i - ih * 7;
        int li = regio(wr * 7 + ih) * 3 + regio(wc * 7 + iw);

        float sv0, sv1;
        {
            int j = lane;
            float s = 0.0f;
            #pragma unroll
            for (int t = 0; t < 8; t++) {
                float4 kv = *(const float4*)&ks[j][t * 4];
                s += q[t].x * kv.x + q[t].y * kv.y + q[t].z * kv.z + q[t].w * kv.w;
            }
            int jh = j / 7, jw = j - jh * 7;
            s += bias_table[((ih - jh + 6) * 13 + (iw - jw + 6)) * NHEAD + head];
            int lj = regio(wr * 7 + jh) * 3 + regio(wc * 7 + jw);
            if (li != lj) s -= 100.0f;
            sv0 = s;
        }
        if (lane < 17) {
            int j = lane + 32;
            float s = 0.0f;
            #pragma unroll
            for (int t = 0; t < 8; t++) {
                float4 kv = *(const float4*)&ks[j][t * 4];
                s += q[t].x * kv.x + q[t].y * kv.y + q[t].z * kv.z + q[t].w * kv.w;
            }
            int jh = j / 7, jw = j - jh * 7;
            s += bias_table[((ih - jh + 6) * 13 + (iw - jw + 6)) * NHEAD + head];
            int lj = regio(wr * 7 + jh) * 3 + regio(wc * 7 + jw);
            if (li != lj) s -= 100.0f;
            sv1 = s;
        } else sv1 = -1e30f;

        float mx = fmaxf(sv0, sv1);
        #pragma unroll
        for (int off = 16; off; off >>= 1) mx = fmaxf(mx, __shfl_xor_sync(~0u, mx, off));
        float e0 = __expf(sv0 - mx);
        float e1 = (lane < 17) ? __expf(sv1 - mx) : 0.0f;
        float sm = e0 + e1;
        #pragma unroll
        for (int off = 16; off; off >>= 1) sm += __shfl_xor_sync(~0u, sm, off);
        float inv = 1.0f / sm;
        S[i][lane] = e0 * inv;
        if (lane < 17) S[i][lane + 32] = e1 * inv;
    }
    __syncthreads();

    size_t obase = (size_t)wi * 49 * 384 + head * 32;
    for (int task = tid; task < 49 * 8; task += 256) {
        int i = task >> 3, d4 = task & 7;
        float ax = 0.f, ay = 0.f, az = 0.f, aw = 0.f;
        #pragma unroll 7
        for (int j = 0; j < 49; j++) {
            float s = S[i][j];
            float4 v = *(const float4*)&vs[j][d4 * 4];
            ax += s * v.x; ay += s * v.y; az += s * v.z; aw += s * v.w;
        }
        __half2* op = (__half2*)&o[obase + (size_t)i * 384 + d4 * 4];
        op[0] = __floats2half2_rn(ax, ay);
        op[1] = __floats2half2_rn(az, aw);
    }
}

// ---------------- host launch ----------------------------------------------
extern "C" void kernel_launch(void* const* d_in, const int* in_sizes, int n_in,
                              void* d_out, int out_size)
{
    const float* x       = (const float*)d_in[0];
    const float* ln1_g   = (const float*)d_in[1];
    const float* ln1_b   = (const float*)d_in[2];
    const float* qkv_w   = (const float*)d_in[3];
    const float* qkv_b   = (const float*)d_in[4];
    const float* proj_w  = (const float*)d_in[5];
    const float* proj_b  = (const float*)d_in[6];
    const float* bias_tb = (const float*)d_in[7];
    const float* ln2_g   = (const float*)d_in[8];
    const float* ln2_b   = (const float*)d_in[9];
    const float* fc1_w   = (const float*)d_in[10];
    const float* fc1_b   = (const float*)d_in[11];
    const float* fc2_w   = (const float*)d_in[12];
    const float* fc2_b   = (const float*)d_in[13];
    float*       out     = (float*)d_out;

    __half *ph, *pqkv, *po, *py, *pu, *pwt;
    float  *pxa;
    cudaGetSymbolAddress((void**)&ph,   g_h);
    cudaGetSymbolAddress((void**)&pqkv, g_qkv);
    cudaGetSymbolAddress((void**)&po,   g_o);
    cudaGetSymbolAddress((void**)&pxa,  g_xa);
    cudaGetSymbolAddress((void**)&py,   g_y);
    cudaGetSymbolAddress((void**)&pu,   g_u);
    cudaGetSymbolAddress((void**)&pwt,  g_wt);

    // 1. LN1 + shift + window gather -> fp16   (launched first so ncu -s 5
    //    lands on the qkv GEMM below)
    ln_kernel<1><<<TOK / 4, 128>>>(x, ln1_g, ln1_b, ph);

    // 0. weight transpose + fp16 convert
    dim3 tb(32, 8);
    transpose_half<<<dim3(1152 / 32,  384 / 32), tb>>>(qkv_w,  pwt + WT_QKV,  384, 1152);
    transpose_half<<<dim3( 384 / 32,  384 / 32), tb>>>(proj_w, pwt + WT_PROJ, 384,  384);
    transpose_half<<<dim3(1536 / 32,  384 / 32), tb>>>(fc1_w,  pwt + WT_FC1,  384, 1536);
    transpose_half<<<dim3( 384 / 32, 1536 / 32), tb>>>(fc2_w,  pwt + WT_FC2, 1536,  384);

    // 2. qkv GEMM [100352 x 1152], K=384 -> fp16
    tc_gemm<0><<<dim3(9, TOK / 128), 256, SMEM_SZ>>>(ph, pwt + WT_QKV, qkv_b, nullptr, pqkv, 1152, 384);

    // 3. windowed attention -> fp16
    attn_kernel<<<2048 * NHEAD, 256>>>(pqkv, bias_tb, po);

    // 4. proj GEMM + window-reverse scatter + residual(x) -> fp32 xa
    tc_gemm<3><<<dim3(3, TOK / 128), 256, SMEM_SZ>>>(po, pwt + WT_PROJ, proj_b, x, pxa, 384, 384);

    // 5. LN2 -> fp16
    ln_kernel<0><<<TOK / 4, 128>>>(pxa, ln2_g, ln2_b, py);

    // 6. fc1 GEMM + gelu, N=1536 -> fp16
    tc_gemm<1><<<dim3(12, TOK / 128), 256, SMEM_SZ>>>(py, pwt + WT_FC1, fc1_b, nullptr, pu, 1536, 384);

    // 7. fc2 GEMM + residual -> fp32 out, K=1536
    tc_gemm<2><<<dim3(3, TOK / 128), 256, SMEM_SZ>>>(pu, pwt + WT_FC2, fc2_b, pxa, out, 384, 1536);
}

// round 12
// speedup vs baseline: 1.5624x; 1.0811x over previous
#include <cuda_runtime.h>
#include <cuda_fp16.h>
#include <math.h>
#include <stdint.h>

// ---------------- problem constants ----------------
#define CDIM    384
#define NHEAD   12
#define TOK     100352        // 32*3136
#define EPS     1e-5f
#define SCALE   0.17677669529663687f  // 1/sqrt(32)

// ---------------- scratch (device globals; no allocations) ----------------
__device__ __half g_h  [(size_t)TOK * 384];
__device__ __half g_qkv[(size_t)TOK * 1152];
__device__ __half g_o  [(size_t)TOK * 384];
__device__ float  g_xa [(size_t)TOK * 384];   // residual stream stays fp32
__device__ __half g_y  [(size_t)TOK * 384];
__device__ __half g_u  [(size_t)TOK * 1536];
__device__ __half g_wt [1769472];             // transposed fp16 weights

#define WT_QKV 0
#define WT_PROJ 442368
#define WT_FC1 589824
#define WT_FC2 1179648

// ---------------- small PTX helpers ----------------
__device__ __forceinline__ uint32_t smem_u32(const void* p){
    uint32_t a;
    asm("{ .reg .u64 t; cvta.to.shared.u64 t, %1; cvt.u32.u64 %0, t; }" : "=r"(a) : "l"(p));
    return a;
}
__device__ __forceinline__ void cp16(uint32_t d, const void* s){
    asm volatile("cp.async.cg.shared.global [%0], [%1], 16;" :: "r"(d), "l"(s));
}
__device__ __forceinline__ void cp_commit(){ asm volatile("cp.async.commit_group;"); }
__device__ __forceinline__ void cp_wait1(){ asm volatile("cp.async.wait_group 1;" ::: "memory"); }
__device__ __forceinline__ void cp_wait0(){ asm volatile("cp.async.wait_group 0;" ::: "memory"); }

// fp16 m16n8k16 mma, fp32 accumulate
__device__ __forceinline__ void mma16(float* d, uint32_t a0, uint32_t a1,
                                      uint32_t a2, uint32_t a3,
                                      uint32_t b0, uint32_t b1){
    asm volatile("mma.sync.aligned.m16n8k16.row.col.f32.f16.f16.f32 "
        "{%0,%1,%2,%3}, {%4,%5,%6,%7}, {%8,%9}, {%0,%1,%2,%3};"
        : "+f"(d[0]), "+f"(d[1]), "+f"(d[2]), "+f"(d[3])
        : "r"(a0), "r"(a1), "r"(a2), "r"(a3), "r"(b0), "r"(b1));
}

__device__ __forceinline__ void ldsm4(uint32_t& r0, uint32_t& r1,
                                      uint32_t& r2, uint32_t& r3, uint32_t addr){
    asm volatile("ldmatrix.sync.aligned.m8n8.x4.shared.b16 {%0,%1,%2,%3}, [%4];"
        : "=r"(r0), "=r"(r1), "=r"(r2), "=r"(r3) : "r"(addr));
}

// window-order row t <-> original-order row (self-inverse map)
__device__ __forceinline__ int winrow_to_orig(int t) {
    int b   = t / 3136;
    int rem = t - b * 3136;
    int w   = rem / 49;
    int n   = rem - w * 49;
    int wr = w >> 3, wc = w & 7;
    int r  = n / 7,  c  = n - r * 7;
    int gh = wr * 7 + r + 3; if (gh >= 56) gh -= 56;
    int gw = wc * 7 + c + 3; if (gw >= 56) gw -= 56;
    return b * 3136 + gh * 56 + gw;
}

// ---------------- LayerNorm -> fp16, warp-per-token, no smem/syncs ---------
template<int GATHER>
__global__ void __launch_bounds__(128) ln_kernel(
    const float* __restrict__ x, const float* __restrict__ g,
    const float* __restrict__ b, __half* __restrict__ out)
{
    int warp = threadIdx.x >> 5, lane = threadIdx.x & 31;
    int t    = (blockIdx.x << 2) + warp;
    int src  = GATHER ? winrow_to_orig(t) : t;

    const float4* xr = (const float4*)(x + (size_t)src * CDIM) + lane * 3;
    float4 v0 = xr[0], v1 = xr[1], v2 = xr[2];

    float s  = v0.x + v0.y + v0.z + v0.w + v1.x + v1.y + v1.z + v1.w
             + v2.x + v2.y + v2.z + v2.w;
    float sq = v0.x*v0.x + v0.y*v0.y + v0.z*v0.z + v0.w*v0.w
             + v1.x*v1.x + v1.y*v1.y + v1.z*v1.z + v1.w*v1.w
             + v2.x*v2.x + v2.y*v2.y + v2.z*v2.z + v2.w*v2.w;
    #pragma unroll
    for (int off = 16; off; off >>= 1) {
        s  += __shfl_xor_sync(~0u, s,  off);
        sq += __shfl_xor_sync(~0u, sq, off);
    }
    float mean = s * (1.0f / CDIM);
    float var  = sq * (1.0f / CDIM) - mean * mean;
    float inv  = rsqrtf(var + EPS);

    const float4* gp = (const float4*)g + lane * 3;
    const float4* bp = (const float4*)b + lane * 3;
    float4 g0 = gp[0], g1 = gp[1], g2 = gp[2];
    float4 b0 = bp[0], b1 = bp[1], b2 = bp[2];

    __half2* op = (__half2*)(out + (size_t)t * CDIM + lane * 12);
    op[0] = __floats2half2_rn((v0.x - mean) * inv * g0.x + b0.x, (v0.y - mean) * inv * g0.y + b0.y);
    op[1] = __floats2half2_rn((v0.z - mean) * inv * g0.z + b0.z, (v0.w - mean) * inv * g0.w + b0.w);
    op[2] = __floats2half2_rn((v1.x - mean) * inv * g1.x + b1.x, (v1.y - mean) * inv * g1.y + b1.y);
    op[3] = __floats2half2_rn((v1.z - mean) * inv * g1.z + b1.z, (v1.w - mean) * inv * g1.w + b1.w);
    op[4] = __floats2half2_rn((v2.x - mean) * inv * g2.x + b2.x, (v2.y - mean) * inv * g2.y + b2.y);
    op[5] = __floats2half2_rn((v2.z - mean) * inv * g2.z + b2.z, (v2.w - mean) * inv * g2.w + b2.w);
}

// ---------------- all 4 weight transposes in ONE launch ---------------------
// in[K,N] fp32 -> out[N,K] fp16, 32x32 tiles
__global__ void __launch_bounds__(256) transpose_all(
    const float* __restrict__ qkv_w, const float* __restrict__ proj_w,
    const float* __restrict__ fc1_w, const float* __restrict__ fc2_w,
    __half* __restrict__ wt)
{
    __shared__ float tile[32][33];
    int bid = blockIdx.x;
    const float* in; __half* out; int K, N, tIdx;
    if (bid < 432)       { in = qkv_w;  out = wt + WT_QKV;  K = 384;  N = 1152; tIdx = bid; }
    else if (bid < 576)  { in = proj_w; out = wt + WT_PROJ; K = 384;  N = 384;  tIdx = bid - 432; }
    else if (bid < 1152) { in = fc1_w;  out = wt + WT_FC1;  K = 384;  N = 1536; tIdx = bid - 576; }
    else                 { in = fc2_w;  out = wt + WT_FC2;  K = 1536; N = 384;  tIdx = bid - 1152; }
    int ntx = N >> 5;
    int by = tIdx / ntx, bx = tIdx - by * ntx;
    int k0 = by * 32, n0 = bx * 32;
    int tx = threadIdx.x & 31, ty = threadIdx.x >> 5;
    #pragma unroll
    for (int i = ty; i < 32; i += 8)
        tile[i][tx] = in[(size_t)(k0 + i) * N + n0 + tx];
    __syncthreads();
    #pragma unroll
    for (int i = ty; i < 32; i += 8)
        out[(size_t)(n0 + i) * K + k0 + tx] = __float2half(tile[tx][i]);
}

// ---------------- FP16 mma.sync GEMM ----------------------------------------
// 128x128 CTA tile, 8 warps in 2x4 grid of 64x32 warp tiles, K staged by 64,
// 2-stage cp.async double buffer, ldmatrix fragment loads.
// Rows padded to 72 halves (144 B) -> ldmatrix phases conflict-free.
// MODE 0: Ch = A*Bt' + bias                 (fp16 out)
// MODE 1: Ch = gelu(A*Bt' + bias)           (fp16 out)
// MODE 2: Cf = A*Bt' + bias + res           (fp32 out)
// MODE 3: Cf[map(row)] = A*Bt' + bias + res[map(row)]  (fp32 out)
#define PITCH_B 144      // bytes per row (72 halves)
#define STG_B   36864    // bytes per stage: 2 matrices * 128 rows * 144 B
#define SMEM_SZ 73728    // 2 stages

template<int MODE>
__global__ void __launch_bounds__(256, 2) tc_gemm(
    const __half* __restrict__ A, const __half* __restrict__ Bt,
    const float* __restrict__ bias, const float* __restrict__ res,
    void* __restrict__ Cv, int N, int K)
{
    extern __shared__ __align__(16) char smem[];
    int tid  = threadIdx.x;
    int lane = tid & 31;
    int wid  = tid >> 5;           // 0..7
    int warp_m = wid & 1;          // 2 x 64 rows
    int warp_n = wid >> 1;         // 4 x 32 cols
    int m0 = blockIdx.y << 7, n0 = blockIdx.x << 7;

    const __half* Arow = A  + (size_t)m0 * K;
    const __half* Brow = Bt + (size_t)n0 * K;
    const int nst = K >> 6;

    uint32_t sbase = smem_u32(smem);

    int ldrow = tid >> 3;          // 0..31 (p adds 32)
    int ldc   = tid & 7;           // 16B chunk (8 halves) within 64-half row

    auto issue_stage = [&](int s, int buf) {
        int kt = s << 6;
        uint32_t bA = sbase + (uint32_t)buf * STG_B;
        uint32_t bB = bA + 18432;
        #pragma unroll
        for (int p = 0; p < 4; ++p) {
            int row = ldrow + (p << 5);
            uint32_t doff = (uint32_t)row * PITCH_B + (uint32_t)(ldc << 4);
            cp16(bA + doff, Arow + (size_t)row * K + kt + (ldc << 3));
            cp16(bB + doff, Brow + (size_t)row * K + kt + (ldc << 3));
        }
        cp_commit();
    };

    float acc[4][4][4];
    #pragma unroll
    for (int i = 0; i < 4; i++)
        #pragma unroll
        for (int j = 0; j < 4; j++)
            #pragma unroll
            for (int r = 0; r < 4; r++) acc[i][j][r] = 0.0f;

    issue_stage(0, 0);

    int lr = lane >> 2;            // 0..7
    int lc = lane & 3;             // 0..3

    uint32_t a_row = (uint32_t)((warp_m << 6) + (lane & 15));
    uint32_t a_off = a_row * PITCH_B + ((uint32_t)(lane >> 4) << 4);
    uint32_t b_row = (uint32_t)((warp_n << 5) + (lane & 7) + (((lane >> 4) & 1) << 3));
    uint32_t b_off = b_row * PITCH_B + (((uint32_t)(lane >> 3) & 1) << 4);

    for (int s = 0; s < nst; ++s) {
        int buf = s & 1;
        __syncthreads();
        if (s + 1 < nst) { issue_stage(s + 1, buf ^ 1); cp_wait1(); }
        else             { cp_wait0(); }
        __syncthreads();

        uint32_t bA = sbase + (uint32_t)buf * STG_B;
        uint32_t bB = bA + 18432;

        #pragma unroll
        for (int kk = 0; kk < 4; kk++) {       // four k16 chunks, 32B apart
            uint32_t a[4][4];
            #pragma unroll
            for (int mt = 0; mt < 4; mt++)
                ldsm4(a[mt][0], a[mt][1], a[mt][2], a[mt][3],
                      bA + a_off + (uint32_t)(mt * 16 * PITCH_B) + (kk << 5));
            uint32_t b[2][4];
            #pragma unroll
            for (int bt = 0; bt < 2; bt++)
                ldsm4(b[bt][0], b[bt][1], b[bt][2], b[bt][3],
                      bB + b_off + (uint32_t)(bt * 16 * PITCH_B) + (kk << 5));
            #pragma unroll
            for (int mt = 0; mt < 4; mt++) {
                mma16(acc[mt][0], a[mt][0], a[mt][1], a[mt][2], a[mt][3], b[0][0], b[0][1]);
                mma16(acc[mt][1], a[mt][0], a[mt][1], a[mt][2], a[mt][3], b[0][2], b[0][3]);
                mma16(acc[mt][2], a[mt][0], a[mt][1], a[mt][2], a[mt][3], b[1][0], b[1][1]);
                mma16(acc[mt][3], a[mt][0], a[mt][1], a[mt][2], a[mt][3], b[1][2], b[1][3]);
            }
        }
    }

    // ---- epilogue ----
    #pragma unroll
    for (int mt = 0; mt < 4; mt++) {
        #pragma unroll
        for (int h = 0; h < 2; h++) {
            int row  = m0 + (warp_m << 6) + (mt << 4) + lr + (h << 3);
            int orow = (MODE == 3) ? winrow_to_orig(row) : row;
            #pragma unroll
            for (int nt = 0; nt < 4; nt++) {
                int c = (warp_n << 5) + (nt << 3) + (lc << 1);
                float2 bv = *(const float2*)(bias + n0 + c);
                float v0 = acc[mt][nt][h * 2 + 0] + bv.x;
                float v1 = acc[mt][nt][h * 2 + 1] + bv.y;
                if (MODE == 1) {
                    v0 = 0.5f * v0 * (1.0f + erff(v0 * 0.70710678118654752f));
                    v1 = 0.5f * v1 * (1.0f + erff(v1 * 0.70710678118654752f));
                }
                if (MODE <= 1) {
                    __half2* dst = (__half2*)((__half*)Cv + (size_t)orow * N + n0 + c);
                    *dst = __floats2half2_rn(v0, v1);
                } else {
                    size_t cb = (size_t)orow * N + n0 + c;
                    float2 rv = *(const float2*)(res + cb);
                    float2 o; o.x = v0 + rv.x; o.y = v1 + rv.y;
                    *(float2*)((float*)Cv + cb) = o;
                }
            }
        }
    }
}

// ---------------- attention: one block per (window, head), conflict-free ---
__device__ __forceinline__ int regio(int g) { return g < 49 ? 0 : (g < 53 ? 1 : 2); }

__global__ void __launch_bounds__(256) attn_kernel(
    const __half* __restrict__ qkv, const float* __restrict__ bias_table,
    __half* __restrict__ o)
{
    int bh   = blockIdx.x;
    int wi   = bh / NHEAD;
    int head = bh - wi * NHEAD;
    int w    = wi & 63;
    int tid  = threadIdx.x;
    int lane = tid & 31;
    int wid  = tid >> 5;

    __shared__ float qs[49][36];
    __shared__ float ks[49][36];
    __shared__ float vs[49][36];
    __shared__ float S [49][49];

    size_t base = (size_t)wi * 49 * 1152 + head * 32;
    for (int e = tid; e < 49 * 32; e += 256) {
        int n = e >> 5, d = e & 31;
        size_t off = base + (size_t)n * 1152 + d;
        qs[n][d] = __half2float(qkv[off]) * SCALE;
        ks[n][d] = __half2float(qkv[off + 384]);
        vs[n][d] = __half2float(qkv[off + 768]);
    }
    __syncthreads();

    int wr = w >> 3, wc = w & 7;

    for (int i = wid; i < 49; i += 8) {
        float4 q[8];
        #pragma unroll
        for (int t = 0; t < 8; t++) q[t] = *(const float4*)&qs[i][t * 4];
        int ih = i / 7, iw = i - ih * 7;
        int li = regio(wr * 7 + ih) * 3 + regio(wc * 7 + iw);

        float sv0, sv1;
        {
            int j = lane;
            float s = 0.0f;
            #pragma unroll
            for (int t = 0; t < 8; t++) {
                float4 kv = *(const float4*)&ks[j][t * 4];
                s += q[t].x * kv.x + q[t].y * kv.y + q[t].z * kv.z + q[t].w * kv.w;
            }
            int jh = j / 7, jw = j - jh * 7;
            s += bias_table[((ih - jh + 6) * 13 + (iw - jw + 6)) * NHEAD + head];
            int lj = regio(wr * 7 + jh) * 3 + regio(wc * 7 + jw);
            if (li != lj) s -= 100.0f;
            sv0 = s;
        }
        if (lane < 17) {
            int j = lane + 32;
            float s = 0.0f;
            #pragma unroll
            for (int t = 0; t < 8; t++) {
                float4 kv = *(const float4*)&ks[j][t * 4];
                s += q[t].x * kv.x + q[t].y * kv.y + q[t].z * kv.z + q[t].w * kv.w;
            }
            int jh = j / 7, jw = j - jh * 7;
            s += bias_table[((ih - jh + 6) * 13 + (iw - jw + 6)) * NHEAD + head];
            int lj = regio(wr * 7 + jh) * 3 + regio(wc * 7 + jw);
            if (li != lj) s -= 100.0f;
            sv1 = s;
        } else sv1 = -1e30f;

        float mx = fmaxf(sv0, sv1);
        #pragma unroll
        for (int off = 16; off; off >>= 1) mx = fmaxf(mx, __shfl_xor_sync(~0u, mx, off));
        float e0 = __expf(sv0 - mx);
        float e1 = (lane < 17) ? __expf(sv1 - mx) : 0.0f;
        float sm = e0 + e1;
        #pragma unroll
        for (int off = 16; off; off >>= 1) sm += __shfl_xor_sync(~0u, sm, off);
        float inv = 1.0f / sm;
        S[i][lane] = e0 * inv;
        if (lane < 17) S[i][lane + 32] = e1 * inv;
    }
    __syncthreads();

    size_t obase = (size_t)wi * 49 * 384 + head * 32;
    for (int task = tid; task < 49 * 8; task += 256) {
        int i = task >> 3, d4 = task & 7;
        float ax = 0.f, ay = 0.f, az = 0.f, aw = 0.f;
        #pragma unroll 7
        for (int j = 0; j < 49; j++) {
            float s = S[i][j];
            float4 v = *(const float4*)&vs[j][d4 * 4];
            ax += s * v.x; ay += s * v.y; az += s * v.z; aw += s * v.w;
        }
        __half2* op = (__half2*)&o[obase + (size_t)i * 384 + d4 * 4];
        op[0] = __floats2half2_rn(ax, ay);
        op[1] = __floats2half2_rn(az, aw);
    }
}

// ---------------- host launch ----------------------------------------------
extern "C" void kernel_launch(void* const* d_in, const int* in_sizes, int n_in,
                              void* d_out, int out_size)
{
    const float* x       = (const float*)d_in[0];
    const float* ln1_g   = (const float*)d_in[1];
    const float* ln1_b   = (const float*)d_in[2];
    const float* qkv_w   = (const float*)d_in[3];
    const float* qkv_b   = (const float*)d_in[4];
    const float* proj_w  = (const float*)d_in[5];
    const float* proj_b  = (const float*)d_in[6];
    const float* bias_tb = (const float*)d_in[7];
    const float* ln2_g   = (const float*)d_in[8];
    const float* ln2_b   = (const float*)d_in[9];
    const float* fc1_w   = (const float*)d_in[10];
    const float* fc1_b   = (const float*)d_in[11];
    const float* fc2_w   = (const float*)d_in[12];
    const float* fc2_b   = (const float*)d_in[13];
    float*       out     = (float*)d_out;

    __half *ph, *pqkv, *po, *py, *pu, *pwt;
    float  *pxa;
    cudaGetSymbolAddress((void**)&ph,   g_h);
    cudaGetSymbolAddress((void**)&pqkv, g_qkv);
    cudaGetSymbolAddress((void**)&po,   g_o);
    cudaGetSymbolAddress((void**)&pxa,  g_xa);
    cudaGetSymbolAddress((void**)&py,   g_y);
    cudaGetSymbolAddress((void**)&pu,   g_u);
    cudaGetSymbolAddress((void**)&pwt,  g_wt);

    // dynamic smem > 48KB needs explicit opt-in (graph-capture compatible)
    cudaFuncSetAttribute(tc_gemm<0>, cudaFuncAttributeMaxDynamicSharedMemorySize, SMEM_SZ);
    cudaFuncSetAttribute(tc_gemm<1>, cudaFuncAttributeMaxDynamicSharedMemorySize, SMEM_SZ);
    cudaFuncSetAttribute(tc_gemm<2>, cudaFuncAttributeMaxDynamicSharedMemorySize, SMEM_SZ);
    cudaFuncSetAttribute(tc_gemm<3>, cudaFuncAttributeMaxDynamicSharedMemorySize, SMEM_SZ);

    // 1. LN1 + shift + window gather -> fp16
    ln_kernel<1><<<TOK / 4, 128>>>(x, ln1_g, ln1_b, ph);

    // 0. all weight transposes in one launch
    transpose_all<<<1728, 256>>>(qkv_w, proj_w, fc1_w, fc2_w, pwt);

    // 2. qkv GEMM [100352 x 1152], K=384 -> fp16
    tc_gemm<0><<<dim3(9, TOK / 128), 256, SMEM_SZ>>>(ph, pwt + WT_QKV, qkv_b, nullptr, pqkv, 1152, 384);

    // 3. windowed attention -> fp16
    attn_kernel<<<2048 * NHEAD, 256>>>(pqkv, bias_tb, po);

    // 4. proj GEMM + window-reverse scatter + residual(x) -> fp32 xa
    tc_gemm<3><<<dim3(3, TOK / 128), 256, SMEM_SZ>>>(po, pwt + WT_PROJ, proj_b, x, pxa, 384, 384);

    // 5. LN2 -> fp16
    ln_kernel<0><<<TOK / 4, 128>>>(pxa, ln2_g, ln2_b, py);

    // 6. fc1 GEMM + gelu, N=1536 -> fp16
    tc_gemm<1><<<dim3(12, TOK / 128), 256, SMEM_SZ>>>(py, pwt + WT_FC1, fc1_b, nullptr, pu, 1536, 384);

    // 7. fc2 GEMM + residual -> fp32 out, K=1536
    tc_gemm<2><<<dim3(3, TOK / 128), 256, SMEM_SZ>>>(pu, pwt + WT_FC2, fc2_b, pxa, out, 384, 1536);
}

// round 13
// speedup vs baseline: 1.7460x; 1.1175x over previous
#include <cuda_runtime.h>
#include <cuda_fp16.h>
#include <math.h>
#include <stdint.h>

// ---------------- problem constants ----------------
#define CDIM    384
#define NHEAD   12
#define TOK     100352        // 32*3136
#define EPS     1e-5f
#define SCALE   0.17677669529663687f  // 1/sqrt(32)

// ---------------- scratch (device globals; no allocations) ----------------
__device__ __half g_h  [(size_t)TOK * 384];
__device__ __half g_qkv[(size_t)TOK * 1152];
__device__ __half g_o  [(size_t)TOK * 384];
__device__ float  g_xa [(size_t)TOK * 384];   // residual stream stays fp32
__device__ __half g_y  [(size_t)TOK * 384];
__device__ __half g_u  [(size_t)TOK * 1536];
__device__ __half g_wt [1769472];             // transposed fp16 weights
__device__ float  g_bias[4 * NHEAD * 2401];   // fused rpb+mask per (type, head)

#define WT_QKV 0
#define WT_PROJ 442368
#define WT_FC1 589824
#define WT_FC2 1179648

// ---------------- small PTX helpers ----------------
__device__ __forceinline__ uint32_t smem_u32(const void* p){
    uint32_t a;
    asm("{ .reg .u64 t; cvta.to.shared.u64 t, %1; cvt.u32.u64 %0, t; }" : "=r"(a) : "l"(p));
    return a;
}
__device__ __forceinline__ void cp16(uint32_t d, const void* s){
    asm volatile("cp.async.cg.shared.global [%0], [%1], 16;" :: "r"(d), "l"(s));
}
__device__ __forceinline__ void cp_commit(){ asm volatile("cp.async.commit_group;"); }
__device__ __forceinline__ void cp_wait1(){ asm volatile("cp.async.wait_group 1;" ::: "memory"); }
__device__ __forceinline__ void cp_wait0(){ asm volatile("cp.async.wait_group 0;" ::: "memory"); }

// fp16 m16n8k16 mma, fp32 accumulate
__device__ __forceinline__ void mma16(float* d, uint32_t a0, uint32_t a1,
                                      uint32_t a2, uint32_t a3,
                                      uint32_t b0, uint32_t b1){
    asm volatile("mma.sync.aligned.m16n8k16.row.col.f32.f16.f16.f32 "
        "{%0,%1,%2,%3}, {%4,%5,%6,%7}, {%8,%9}, {%0,%1,%2,%3};"
        : "+f"(d[0]), "+f"(d[1]), "+f"(d[2]), "+f"(d[3])
        : "r"(a0), "r"(a1), "r"(a2), "r"(a3), "r"(b0), "r"(b1));
}

__device__ __forceinline__ void ldsm4(uint32_t& r0, uint32_t& r1,
                                      uint32_t& r2, uint32_t& r3, uint32_t addr){
    asm volatile("ldmatrix.sync.aligned.m8n8.x4.shared.b16 {%0,%1,%2,%3}, [%4];"
        : "=r"(r0), "=r"(r1), "=r"(r2), "=r"(r3) : "r"(addr));
}

// window-order row t <-> original-order row (self-inverse map)
__device__ __forceinline__ int winrow_to_orig(int t) {
    int b   = t / 3136;
    int rem = t - b * 3136;
    int w   = rem / 49;
    int n   = rem - w * 49;
    int wr = w >> 3, wc = w & 7;
    int r  = n / 7,  c  = n - r * 7;
    int gh = wr * 7 + r + 3; if (gh >= 56) gh -= 56;
    int gw = wc * 7 + c + 3; if (gw >= 56) gw -= 56;
    return b * 3136 + gh * 56 + gw;
}

// ---------------- LayerNorm -> fp16, warp-per-token, no smem/syncs ---------
template<int GATHER>
__global__ void __launch_bounds__(128) ln_kernel(
    const float* __restrict__ x, const float* __restrict__ g,
    const float* __restrict__ b, __half* __restrict__ out)
{
    int warp = threadIdx.x >> 5, lane = threadIdx.x & 31;
    int t    = (blockIdx.x << 2) + warp;
    int src  = GATHER ? winrow_to_orig(t) : t;

    const float4* xr = (const float4*)(x + (size_t)src * CDIM) + lane * 3;
    float4 v0 = xr[0], v1 = xr[1], v2 = xr[2];

    float s  = v0.x + v0.y + v0.z + v0.w + v1.x + v1.y + v1.z + v1.w
             + v2.x + v2.y + v2.z + v2.w;
    float sq = v0.x*v0.x + v0.y*v0.y + v0.z*v0.z + v0.w*v0.w
             + v1.x*v1.x + v1.y*v1.y + v1.z*v1.z + v1.w*v1.w
             + v2.x*v2.x + v2.y*v2.y + v2.z*v2.z + v2.w*v2.w;
    #pragma unroll
    for (int off = 16; off; off >>= 1) {
        s  += __shfl_xor_sync(~0u, s,  off);
        sq += __shfl_xor_sync(~0u, sq, off);
    }
    float mean = s * (1.0f / CDIM);
    float var  = sq * (1.0f / CDIM) - mean * mean;
    float inv  = rsqrtf(var + EPS);

    const float4* gp = (const float4*)g + lane * 3;
    const float4* bp = (const float4*)b + lane * 3;
    float4 g0 = gp[0], g1 = gp[1], g2 = gp[2];
    float4 b0 = bp[0], b1 = bp[1], b2 = bp[2];

    __half2* op = (__half2*)(out + (size_t)t * CDIM + lane * 12);
    op[0] = __floats2half2_rn((v0.x - mean) * inv * g0.x + b0.x, (v0.y - mean) * inv * g0.y + b0.y);
    op[1] = __floats2half2_rn((v0.z - mean) * inv * g0.z + b0.z, (v0.w - mean) * inv * g0.w + b0.w);
    op[2] = __floats2half2_rn((v1.x - mean) * inv * g1.x + b1.x, (v1.y - mean) * inv * g1.y + b1.y);
    op[3] = __floats2half2_rn((v1.z - mean) * inv * g1.z + b1.z, (v1.w - mean) * inv * g1.w + b1.w);
    op[4] = __floats2half2_rn((v2.x - mean) * inv * g2.x + b2.x, (v2.y - mean) * inv * g2.y + b2.y);
    op[5] = __floats2half2_rn((v2.z - mean) * inv * g2.z + b2.z, (v2.w - mean) * inv * g2.w + b2.w);
}

// ---------------- all 4 weight transposes in ONE launch ---------------------
__global__ void __launch_bounds__(256) transpose_all(
    const float* __restrict__ qkv_w, const float* __restrict__ proj_w,
    const float* __restrict__ fc1_w, const float* __restrict__ fc2_w,
    __half* __restrict__ wt)
{
    __shared__ float tile[32][33];
    int bid = blockIdx.x;
    const float* in; __half* out; int K, N, tIdx;
    if (bid < 432)       { in = qkv_w;  out = wt + WT_QKV;  K = 384;  N = 1152; tIdx = bid; }
    else if (bid < 576)  { in = proj_w; out = wt + WT_PROJ; K = 384;  N = 384;  tIdx = bid - 432; }
    else if (bid < 1152) { in = fc1_w;  out = wt + WT_FC1;  K = 384;  N = 1536; tIdx = bid - 576; }
    else                 { in = fc2_w;  out = wt + WT_FC2;  K = 1536; N = 384;  tIdx = bid - 1152; }
    int ntx = N >> 5;
    int by = tIdx / ntx, bx = tIdx - by * ntx;
    int k0 = by * 32, n0 = bx * 32;
    int tx = threadIdx.x & 31, ty = threadIdx.x >> 5;
    #pragma unroll
    for (int i = ty; i < 32; i += 8)
        tile[i][tx] = in[(size_t)(k0 + i) * N + n0 + tx];
    __syncthreads();
    #pragma unroll
    for (int i = ty; i < 32; i += 8)
        out[(size_t)(n0 + i) * K + k0 + tx] = __float2half(tile[tx][i]);
}

// ---------------- fused rel-pos bias + shifted-window mask -----------------
// blockIdx.x = type*NHEAD + head; type = (wr==7)*2 + (wc==7)
__global__ void __launch_bounds__(256) prep_bias(
    const float* __restrict__ bias_table, float* __restrict__ gb)
{
    int type = blockIdx.x / NHEAD, head = blockIdx.x - type * NHEAD;
    int rowB = type >> 1, colB = type & 1;
    for (int e = threadIdx.x; e < 2401; e += 256) {
        int i = e / 49, j = e - i * 49;
        int ih = i / 7, iw = i - ih * 7;
        int jh = j / 7, jw = j - jh * 7;
        float v = bias_table[((ih - jh + 6) * 13 + (iw - jw + 6)) * NHEAD + head];
        int li = (rowB ? (ih < 4 ? 1 : 2) : 0) * 3 + (colB ? (iw < 4 ? 1 : 2) : 0);
        int lj = (rowB ? (jh < 4 ? 1 : 2) : 0) * 3 + (colB ? (jw < 4 ? 1 : 2) : 0);
        if (li != lj) v -= 100.0f;
        gb[blockIdx.x * 2401 + e] = v;
    }
}

// ---------------- FP16 mma.sync GEMM ----------------------------------------
#define PITCH_B 144      // bytes per row (72 halves)
#define STG_B   36864    // bytes per stage
#define SMEM_SZ 73728    // 2 stages

template<int MODE>
__global__ void __launch_bounds__(256, 2) tc_gemm(
    const __half* __restrict__ A, const __half* __restrict__ Bt,
    const float* __restrict__ bias, const float* __restrict__ res,
    void* __restrict__ Cv, int N, int K)
{
    extern __shared__ __align__(16) char smem[];
    int tid  = threadIdx.x;
    int lane = tid & 31;
    int wid  = tid >> 5;           // 0..7
    int warp_m = wid & 1;          // 2 x 64 rows
    int warp_n = wid >> 1;         // 4 x 32 cols
    int m0 = blockIdx.y << 7, n0 = blockIdx.x << 7;

    const __half* Arow = A  + (size_t)m0 * K;
    const __half* Brow = Bt + (size_t)n0 * K;
    const int nst = K >> 6;

    uint32_t sbase = smem_u32(smem);

    int ldrow = tid >> 3;
    int ldc   = tid & 7;

    auto issue_stage = [&](int s, int buf) {
        int kt = s << 6;
        uint32_t bA = sbase + (uint32_t)buf * STG_B;
        uint32_t bB = bA + 18432;
        #pragma unroll
        for (int p = 0; p < 4; ++p) {
            int row = ldrow + (p << 5);
            uint32_t doff = (uint32_t)row * PITCH_B + (uint32_t)(ldc << 4);
            cp16(bA + doff, Arow + (size_t)row * K + kt + (ldc << 3));
            cp16(bB + doff, Brow + (size_t)row * K + kt + (ldc << 3));
        }
        cp_commit();
    };

    float acc[4][4][4];
    #pragma unroll
    for (int i = 0; i < 4; i++)
        #pragma unroll
        for (int j = 0; j < 4; j++)
            #pragma unroll
            for (int r = 0; r < 4; r++) acc[i][j][r] = 0.0f;

    issue_stage(0, 0);

    int lr = lane >> 2;
    int lc = lane & 3;

    uint32_t a_row = (uint32_t)((warp_m << 6) + (lane & 15));
    uint32_t a_off = a_row * PITCH_B + ((uint32_t)(lane >> 4) << 4);
    uint32_t b_row = (uint32_t)((warp_n << 5) + (lane & 7) + (((lane >> 4) & 1) << 3));
    uint32_t b_off = b_row * PITCH_B + (((uint32_t)(lane >> 3) & 1) << 4);

    for (int s = 0; s < nst; ++s) {
        int buf = s & 1;
        __syncthreads();
        if (s + 1 < nst) { issue_stage(s + 1, buf ^ 1); cp_wait1(); }
        else             { cp_wait0(); }
        __syncthreads();

        uint32_t bA = sbase + (uint32_t)buf * STG_B;
        uint32_t bB = bA + 18432;

        #pragma unroll
        for (int kk = 0; kk < 4; kk++) {
            uint32_t a[4][4];
            #pragma unroll
            for (int mt = 0; mt < 4; mt++)
                ldsm4(a[mt][0], a[mt][1], a[mt][2], a[mt][3],
                      bA + a_off + (uint32_t)(mt * 16 * PITCH_B) + (kk << 5));
            uint32_t b[2][4];
            #pragma unroll
            for (int bt = 0; bt < 2; bt++)
                ldsm4(b[bt][0], b[bt][1], b[bt][2], b[bt][3],
                      bB + b_off + (uint32_t)(bt * 16 * PITCH_B) + (kk << 5));
            #pragma unroll
            for (int mt = 0; mt < 4; mt++) {
                mma16(acc[mt][0], a[mt][0], a[mt][1], a[mt][2], a[mt][3], b[0][0], b[0][1]);
                mma16(acc[mt][1], a[mt][0], a[mt][1], a[mt][2], a[mt][3], b[0][2], b[0][3]);
                mma16(acc[mt][2], a[mt][0], a[mt][1], a[mt][2], a[mt][3], b[1][0], b[1][1]);
                mma16(acc[mt][3], a[mt][0], a[mt][1], a[mt][2], a[mt][3], b[1][2], b[1][3]);
            }
        }
    }

    // ---- epilogue ----
    #pragma unroll
    for (int mt = 0; mt < 4; mt++) {
        #pragma unroll
        for (int h = 0; h < 2; h++) {
            int row  = m0 + (warp_m << 6) + (mt << 4) + lr + (h << 3);
            int orow = (MODE == 3) ? winrow_to_orig(row) : row;
            #pragma unroll
            for (int nt = 0; nt < 4; nt++) {
                int c = (warp_n << 5) + (nt << 3) + (lc << 1);
                float2 bv = *(const float2*)(bias + n0 + c);
                float v0 = acc[mt][nt][h * 2 + 0] + bv.x;
                float v1 = acc[mt][nt][h * 2 + 1] + bv.y;
                if (MODE == 1) {
                    v0 = 0.5f * v0 * (1.0f + erff(v0 * 0.70710678118654752f));
                    v1 = 0.5f * v1 * (1.0f + erff(v1 * 0.70710678118654752f));
                }
                if (MODE <= 1) {
                    __half2* dst = (__half2*)((__half*)Cv + (size_t)orow * N + n0 + c);
                    *dst = __floats2half2_rn(v0, v1);
                } else {
                    size_t cb = (size_t)orow * N + n0 + c;
                    float2 rv = *(const float2*)(res + cb);
                    float2 o; o.x = v0 + rv.x; o.y = v1 + rv.y;
                    *(float2*)((float*)Cv + cb) = o;
                }
            }
        }
    }
}

// ---------------- attention: 128 threads per (window, head) ----------------
__global__ void __launch_bounds__(128, 6) attn_kernel(
    const __half* __restrict__ qkv, const float* __restrict__ bfused,
    __half* __restrict__ o)
{
    int bh   = blockIdx.x;
    int wi   = bh / NHEAD;
    int head = bh - wi * NHEAD;
    int w    = wi & 63;
    int tid  = threadIdx.x;
    int lane = tid & 31;
    int wid  = tid >> 5;           // 0..3
    int type = (((w >> 3) == 7) ? 2 : 0) + (((w & 7) == 7) ? 1 : 0);

    __shared__ float qs[49][36];
    __shared__ float ks[49][36];
    __shared__ float vs[49][36];
    __shared__ float S [49][49];

    // vectorized load: 196 tasks, each 8 halves per matrix
    size_t base = (size_t)wi * 49 * 1152 + head * 32;
    for (int e = tid; e < 196; e += 128) {
        int n = e >> 2, c = e & 3;
        const __half* src = qkv + base + (size_t)n * 1152 + (c << 3);
        uint4 qv = *(const uint4*)(src);
        uint4 kv = *(const uint4*)(src + 384);
        uint4 vv = *(const uint4*)(src + 768);
        const __half2* qh = (const __half2*)&qv;
        const __half2* kh = (const __half2*)&kv;
        const __half2* vh = (const __half2*)&vv;
        #pragma unroll
        for (int t = 0; t < 4; t++) {
            float2 fq = __half22float2(qh[t]);
            float2 fk = __half22float2(kh[t]);
            float2 fv = __half22float2(vh[t]);
            qs[n][(c << 3) + 2*t    ] = fq.x * SCALE;
            qs[n][(c << 3) + 2*t + 1] = fq.y * SCALE;
            ks[n][(c << 3) + 2*t    ] = fk.x;
            ks[n][(c << 3) + 2*t + 1] = fk.y;
            vs[n][(c << 3) + 2*t    ] = fv.x;
            vs[n][(c << 3) + 2*t + 1] = fv.y;
        }
    }
    __syncthreads();

    const float* Bf = bfused + (size_t)(type * NHEAD + head) * 2401;

    // QK^T + fused bias + softmax: one warp per row
    for (int i = wid; i < 49; i += 4) {
        float4 q[8];
        #pragma unroll
        for (int t = 0; t < 8; t++) q[t] = *(const float4*)&qs[i][t * 4];
        const float* Br = Bf + i * 49;

        float sv0, sv1;
        {
            int j = lane;
            float s = Br[j];
            #pragma unroll
            for (int t = 0; t < 8; t++) {
                float4 kv = *(const float4*)&ks[j][t * 4];
                s += q[t].x * kv.x + q[t].y * kv.y + q[t].z * kv.z + q[t].w * kv.w;
            }
            sv0 = s;
        }
        if (lane < 17) {
            int j = lane + 32;
            float s = Br[j];
            #pragma unroll
            for (int t = 0; t < 8; t++) {
                float4 kv = *(const float4*)&ks[j][t * 4];
                s += q[t].x * kv.x + q[t].y * kv.y + q[t].z * kv.z + q[t].w * kv.w;
            }
            sv1 = s;
        } else sv1 = -1e30f;

        float mx = fmaxf(sv0, sv1);
        #pragma unroll
        for (int off = 16; off; off >>= 1) mx = fmaxf(mx, __shfl_xor_sync(~0u, mx, off));
        float e0 = __expf(sv0 - mx);
        float e1 = (lane < 17) ? __expf(sv1 - mx) : 0.0f;
        float sm = e0 + e1;
        #pragma unroll
        for (int off = 16; off; off >>= 1) sm += __shfl_xor_sync(~0u, sm, off);
        float inv = 1.0f / sm;
        S[i][lane] = e0 * inv;
        if (lane < 17) S[i][lane + 32] = e1 * inv;
    }
    __syncthreads();

    // AV: task = (row i, d-quad)
    size_t obase = (size_t)wi * 49 * 384 + head * 32;
    for (int task = tid; task < 49 * 8; task += 128) {
        int i = task >> 3, d4 = task & 7;
        float ax = 0.f, ay = 0.f, az = 0.f, aw = 0.f;
        #pragma unroll 7
        for (int j = 0; j < 49; j++) {
            float s = S[i][j];
            float4 v = *(const float4*)&vs[j][d4 * 4];
            ax += s * v.x; ay += s * v.y; az += s * v.z; aw += s * v.w;
        }
        __half2* op = (__half2*)&o[obase + (size_t)i * 384 + d4 * 4];
        op[0] = __floats2half2_rn(ax, ay);
        op[1] = __floats2half2_rn(az, aw);
    }
}

// ---------------- host launch ----------------------------------------------
extern "C" void kernel_launch(void* const* d_in, const int* in_sizes, int n_in,
                              void* d_out, int out_size)
{
    const float* x       = (const float*)d_in[0];
    const float* ln1_g   = (const float*)d_in[1];
    const float* ln1_b   = (const float*)d_in[2];
    const float* qkv_w   = (const float*)d_in[3];
    const float* qkv_b   = (const float*)d_in[4];
    const float* proj_w  = (const float*)d_in[5];
    const float* proj_b  = (const float*)d_in[6];
    const float* bias_tb = (const float*)d_in[7];
    const float* ln2_g   = (const float*)d_in[8];
    const float* ln2_b   = (const float*)d_in[9];
    const float* fc1_w   = (const float*)d_in[10];
    const float* fc1_b   = (const float*)d_in[11];
    const float* fc2_w   = (const float*)d_in[12];
    const float* fc2_b   = (const float*)d_in[13];
    float*       out     = (float*)d_out;

    __half *ph, *pqkv, *po, *py, *pu, *pwt;
    float  *pxa, *pbias;
    cudaGetSymbolAddress((void**)&ph,   g_h);
    cudaGetSymbolAddress((void**)&pqkv, g_qkv);
    cudaGetSymbolAddress((void**)&po,   g_o);
    cudaGetSymbolAddress((void**)&pxa,  g_xa);
    cudaGetSymbolAddress((void**)&py,   g_y);
    cudaGetSymbolAddress((void**)&pu,   g_u);
    cudaGetSymbolAddress((void**)&pwt,  g_wt);
    cudaGetSymbolAddress((void**)&pbias, g_bias);

    cudaFuncSetAttribute(tc_gemm<0>, cudaFuncAttributeMaxDynamicSharedMemorySize, SMEM_SZ);
    cudaFuncSetAttribute(tc_gemm<1>, cudaFuncAttributeMaxDynamicSharedMemorySize, SMEM_SZ);
    cudaFuncSetAttribute(tc_gemm<2>, cudaFuncAttributeMaxDynamicSharedMemorySize, SMEM_SZ);
    cudaFuncSetAttribute(tc_gemm<3>, cudaFuncAttributeMaxDynamicSharedMemorySize, SMEM_SZ);

    // 1. LN1 + shift + window gather -> fp16
    ln_kernel<1><<<TOK / 4, 128>>>(x, ln1_g, ln1_b, ph);

    // 0a. all weight transposes in one launch
    transpose_all<<<1728, 256>>>(qkv_w, proj_w, fc1_w, fc2_w, pwt);

    // 0b. fused bias+mask tables (4 types x 12 heads)
    prep_bias<<<4 * NHEAD, 256>>>(bias_tb, pbias);

    // 2. qkv GEMM [100352 x 1152], K=384 -> fp16
    tc_gemm<0><<<dim3(9, TOK / 128), 256, SMEM_SZ>>>(ph, pwt + WT_QKV, qkv_b, nullptr, pqkv, 1152, 384);

    // 3. windowed attention -> fp16
    attn_kernel<<<2048 * NHEAD, 128>>>(pqkv, pbias, po);

    // 4. proj GEMM + window-reverse scatter + residual(x) -> fp32 xa
    tc_gemm<3><<<dim3(3, TOK / 128), 256, SMEM_SZ>>>(po, pwt + WT_PROJ, proj_b, x, pxa, 384, 384);

    // 5. LN2 -> fp16
    ln_kernel<0><<<TOK / 4, 128>>>(pxa, ln2_g, ln2_b, py);

    // 6. fc1 GEMM + gelu, N=1536 -> fp16
    tc_gemm<1><<<dim3(12, TOK / 128), 256, SMEM_SZ>>>(py, pwt + WT_FC1, fc1_b, nullptr, pu, 1536, 384);

    // 7. fc2 GEMM + residual -> fp32 out, K=1536
    tc_gemm<2><<<dim3(3, TOK / 128), 256, SMEM_SZ>>>(pu, pwt + WT_FC2, fc2_b, pxa, out, 384, 1536);
}

// round 14
// speedup vs baseline: 1.7606x; 1.0084x over previous
#include <cuda_runtime.h>
#include <cuda_fp16.h>
#include <math.h>
#include <stdint.h>

// ---------------- problem constants ----------------
#define CDIM    384
#define NHEAD   12
#define TOK     100352        // 32*3136
#define EPS     1e-5f
#define SCALE   0.17677669529663687f  // 1/sqrt(32)

// ---------------- scratch (device globals; no allocations) ----------------
__device__ __half g_h  [(size_t)TOK * 384];
__device__ __half g_qkv[(size_t)TOK * 1152];
__device__ __half g_o  [(size_t)TOK * 384];
__device__ float  g_xa [(size_t)TOK * 384];   // residual stream stays fp32
__device__ __half g_y  [(size_t)TOK * 384];
__device__ __half g_u  [(size_t)TOK * 1536];
__device__ __half g_wt [1769472];             // transposed fp16 weights
__device__ float  g_bias[4 * NHEAD * 2401];   // fused rpb+mask per (type, head)

#define WT_QKV 0
#define WT_PROJ 442368
#define WT_FC1 589824
#define WT_FC2 1179648

// ---------------- small PTX helpers ----------------
__device__ __forceinline__ uint32_t smem_u32(const void* p){
    uint32_t a;
    asm("{ .reg .u64 t; cvta.to.shared.u64 t, %1; cvt.u32.u64 %0, t; }" : "=r"(a) : "l"(p));
    return a;
}
__device__ __forceinline__ void cp16(uint32_t d, const void* s){
    asm volatile("cp.async.cg.shared.global [%0], [%1], 16;" :: "r"(d), "l"(s));
}
__device__ __forceinline__ void cp_commit(){ asm volatile("cp.async.commit_group;"); }
__device__ __forceinline__ void cp_wait1(){ asm volatile("cp.async.wait_group 1;" ::: "memory"); }
__device__ __forceinline__ void cp_wait0(){ asm volatile("cp.async.wait_group 0;" ::: "memory"); }

// fp16 m16n8k16 mma, fp32 accumulate
__device__ __forceinline__ void mma16(float* d, uint32_t a0, uint32_t a1,
                                      uint32_t a2, uint32_t a3,
                                      uint32_t b0, uint32_t b1){
    asm volatile("mma.sync.aligned.m16n8k16.row.col.f32.f16.f16.f32 "
        "{%0,%1,%2,%3}, {%4,%5,%6,%7}, {%8,%9}, {%0,%1,%2,%3};"
        : "+f"(d[0]), "+f"(d[1]), "+f"(d[2]), "+f"(d[3])
        : "r"(a0), "r"(a1), "r"(a2), "r"(a3), "r"(b0), "r"(b1));
}

__device__ __forceinline__ void ldsm4(uint32_t& r0, uint32_t& r1,
                                      uint32_t& r2, uint32_t& r3, uint32_t addr){
    asm volatile("ldmatrix.sync.aligned.m8n8.x4.shared.b16 {%0,%1,%2,%3}, [%4];"
        : "=r"(r0), "=r"(r1), "=r"(r2), "=r"(r3) : "r"(addr));
}

// window-order row t <-> original-order row (self-inverse map)
__device__ __forceinline__ int winrow_to_orig(int t) {
    int b   = t / 3136;
    int rem = t - b * 3136;
    int w   = rem / 49;
    int n   = rem - w * 49;
    int wr = w >> 3, wc = w & 7;
    int r  = n / 7,  c  = n - r * 7;
    int gh = wr * 7 + r + 3; if (gh >= 56) gh -= 56;
    int gw = wc * 7 + c + 3; if (gw >= 56) gw -= 56;
    return b * 3136 + gh * 56 + gw;
}

// ---------------- LayerNorm -> fp16, warp-per-token, no smem/syncs ---------
template<int GATHER>
__global__ void __launch_bounds__(128) ln_kernel(
    const float* __restrict__ x, const float* __restrict__ g,
    const float* __restrict__ b, __half* __restrict__ out)
{
    int warp = threadIdx.x >> 5, lane = threadIdx.x & 31;
    int t    = (blockIdx.x << 2) + warp;
    int src  = GATHER ? winrow_to_orig(t) : t;

    const float4* xr = (const float4*)(x + (size_t)src * CDIM) + lane * 3;
    float4 v0 = xr[0], v1 = xr[1], v2 = xr[2];

    float s  = v0.x + v0.y + v0.z + v0.w + v1.x + v1.y + v1.z + v1.w
             + v2.x + v2.y + v2.z + v2.w;
    float sq = v0.x*v0.x + v0.y*v0.y + v0.z*v0.z + v0.w*v0.w
             + v1.x*v1.x + v1.y*v1.y + v1.z*v1.z + v1.w*v1.w
             + v2.x*v2.x + v2.y*v2.y + v2.z*v2.z + v2.w*v2.w;
    #pragma unroll
    for (int off = 16; off; off >>= 1) {
        s  += __shfl_xor_sync(~0u, s,  off);
        sq += __shfl_xor_sync(~0u, sq, off);
    }
    float mean = s * (1.0f / CDIM);
    float var  = sq * (1.0f / CDIM) - mean * mean;
    float inv  = rsqrtf(var + EPS);

    const float4* gp = (const float4*)g + lane * 3;
    const float4* bp = (const float4*)b + lane * 3;
    float4 g0 = gp[0], g1 = gp[1], g2 = gp[2];
    float4 b0 = bp[0], b1 = bp[1], b2 = bp[2];

    __half2* op = (__half2*)(out + (size_t)t * CDIM + lane * 12);
    op[0] = __floats2half2_rn((v0.x - mean) * inv * g0.x + b0.x, (v0.y - mean) * inv * g0.y + b0.y);
    op[1] = __floats2half2_rn((v0.z - mean) * inv * g0.z + b0.z, (v0.w - mean) * inv * g0.w + b0.w);
    op[2] = __floats2half2_rn((v1.x - mean) * inv * g1.x + b1.x, (v1.y - mean) * inv * g1.y + b1.y);
    op[3] = __floats2half2_rn((v1.z - mean) * inv * g1.z + b1.z, (v1.w - mean) * inv * g1.w + b1.w);
    op[4] = __floats2half2_rn((v2.x - mean) * inv * g2.x + b2.x, (v2.y - mean) * inv * g2.y + b2.y);
    op[5] = __floats2half2_rn((v2.z - mean) * inv * g2.z + b2.z, (v2.w - mean) * inv * g2.w + b2.w);
}

// ---------------- all 4 weight transposes in ONE launch ---------------------
__global__ void __launch_bounds__(256) transpose_all(
    const float* __restrict__ qkv_w, const float* __restrict__ proj_w,
    const float* __restrict__ fc1_w, const float* __restrict__ fc2_w,
    __half* __restrict__ wt)
{
    __shared__ float tile[32][33];
    int bid = blockIdx.x;
    const float* in; __half* out; int K, N, tIdx;
    if (bid < 432)       { in = qkv_w;  out = wt + WT_QKV;  K = 384;  N = 1152; tIdx = bid; }
    else if (bid < 576)  { in = proj_w; out = wt + WT_PROJ; K = 384;  N = 384;  tIdx = bid - 432; }
    else if (bid < 1152) { in = fc1_w;  out = wt + WT_FC1;  K = 384;  N = 1536; tIdx = bid - 576; }
    else                 { in = fc2_w;  out = wt + WT_FC2;  K = 1536; N = 384;  tIdx = bid - 1152; }
    int ntx = N >> 5;
    int by = tIdx / ntx, bx = tIdx - by * ntx;
    int k0 = by * 32, n0 = bx * 32;
    int tx = threadIdx.x & 31, ty = threadIdx.x >> 5;
    #pragma unroll
    for (int i = ty; i < 32; i += 8)
        tile[i][tx] = in[(size_t)(k0 + i) * N + n0 + tx];
    __syncthreads();
    #pragma unroll
    for (int i = ty; i < 32; i += 8)
        out[(size_t)(n0 + i) * K + k0 + tx] = __float2half(tile[tx][i]);
}

// ---------------- fused rel-pos bias + shifted-window mask -----------------
__global__ void __launch_bounds__(256) prep_bias(
    const float* __restrict__ bias_table, float* __restrict__ gb)
{
    int type = blockIdx.x / NHEAD, head = blockIdx.x - type * NHEAD;
    int rowB = type >> 1, colB = type & 1;
    for (int e = threadIdx.x; e < 2401; e += 256) {
        int i = e / 49, j = e - i * 49;
        int ih = i / 7, iw = i - ih * 7;
        int jh = j / 7, jw = j - jh * 7;
        float v = bias_table[((ih - jh + 6) * 13 + (iw - jw + 6)) * NHEAD + head];
        int li = (rowB ? (ih < 4 ? 1 : 2) : 0) * 3 + (colB ? (iw < 4 ? 1 : 2) : 0);
        int lj = (rowB ? (jh < 4 ? 1 : 2) : 0) * 3 + (colB ? (jw < 4 ? 1 : 2) : 0);
        if (li != lj) v -= 100.0f;
        gb[blockIdx.x * 2401 + e] = v;
    }
}

// ---------------- FP16 mma.sync GEMM ----------------------------------------
// 128x128 CTA tile, 8 warps (2x4 of 64x32), K staged by 64,
// 3-stage cp.async pipeline with ONE barrier per stage.
#define PITCH_B 144      // bytes per row (72 halves)
#define STG_B   36864    // bytes per stage
#define SMEM_SZ 110592   // 3 stages

template<int MODE>
__global__ void __launch_bounds__(256, 2) tc_gemm(
    const __half* __restrict__ A, const __half* __restrict__ Bt,
    const float* __restrict__ bias, const float* __restrict__ res,
    void* __restrict__ Cv, int N, int K)
{
    extern __shared__ __align__(16) char smem[];
    int tid  = threadIdx.x;
    int lane = tid & 31;
    int wid  = tid >> 5;           // 0..7
    int warp_m = wid & 1;          // 2 x 64 rows
    int warp_n = wid >> 1;         // 4 x 32 cols
    int m0 = blockIdx.y << 7, n0 = blockIdx.x << 7;

    const __half* Arow = A  + (size_t)m0 * K;
    const __half* Brow = Bt + (size_t)n0 * K;
    const int nst = K >> 6;

    uint32_t sbase = smem_u32(smem);

    int ldrow = tid >> 3;
    int ldc   = tid & 7;

    auto issue_stage = [&](int s, int buf) {
        int kt = s << 6;
        uint32_t bA = sbase + (uint32_t)buf * STG_B;
        uint32_t bB = bA + 18432;
        #pragma unroll
        for (int p = 0; p < 4; ++p) {
            int row = ldrow + (p << 5);
            uint32_t doff = (uint32_t)row * PITCH_B + (uint32_t)(ldc << 4);
            cp16(bA + doff, Arow + (size_t)row * K + kt + (ldc << 3));
            cp16(bB + doff, Brow + (size_t)row * K + kt + (ldc << 3));
        }
        cp_commit();
    };

    float acc[4][4][4];
    #pragma unroll
    for (int i = 0; i < 4; i++)
        #pragma unroll
        for (int j = 0; j < 4; j++)
            #pragma unroll
            for (int r = 0; r < 4; r++) acc[i][j][r] = 0.0f;

    issue_stage(0, 0);
    issue_stage(1, 1);

    int lr = lane >> 2;
    int lc = lane & 3;

    uint32_t a_row = (uint32_t)((warp_m << 6) + (lane & 15));
    uint32_t a_off = a_row * PITCH_B + ((uint32_t)(lane >> 4) << 4);
    uint32_t b_row = (uint32_t)((warp_n << 5) + (lane & 7) + (((lane >> 4) & 1) << 3));
    uint32_t b_off = b_row * PITCH_B + (((uint32_t)(lane >> 3) & 1) << 4);

    for (int s = 0; s < nst; ++s) {
        int buf = s % 3;
        if (s == nst - 1) cp_wait0(); else cp_wait1();
        __syncthreads();   // stage s visible; all threads done computing s-1
        if (s + 2 < nst) issue_stage(s + 2, (s + 2) % 3);

        uint32_t bA = sbase + (uint32_t)buf * STG_B;
        uint32_t bB = bA + 18432;

        #pragma unroll
        for (int kk = 0; kk < 4; kk++) {
            uint32_t a[4][4];
            #pragma unroll
            for (int mt = 0; mt < 4; mt++)
                ldsm4(a[mt][0], a[mt][1], a[mt][2], a[mt][3],
                      bA + a_off + (uint32_t)(mt * 16 * PITCH_B) + (kk << 5));
            uint32_t b[2][4];
            #pragma unroll
            for (int bt = 0; bt < 2; bt++)
                ldsm4(b[bt][0], b[bt][1], b[bt][2], b[bt][3],
                      bB + b_off + (uint32_t)(bt * 16 * PITCH_B) + (kk << 5));
            #pragma unroll
            for (int mt = 0; mt < 4; mt++) {
                mma16(acc[mt][0], a[mt][0], a[mt][1], a[mt][2], a[mt][3], b[0][0], b[0][1]);
                mma16(acc[mt][1], a[mt][0], a[mt][1], a[mt][2], a[mt][3], b[0][2], b[0][3]);
                mma16(acc[mt][2], a[mt][0], a[mt][1], a[mt][2], a[mt][3], b[1][0], b[1][1]);
                mma16(acc[mt][3], a[mt][0], a[mt][1], a[mt][2], a[mt][3], b[1][2], b[1][3]);
            }
        }
    }

    // ---- epilogue ----
    #pragma unroll
    for (int mt = 0; mt < 4; mt++) {
        #pragma unroll
        for (int h = 0; h < 2; h++) {
            int row  = m0 + (warp_m << 6) + (mt << 4) + lr + (h << 3);
            int orow = (MODE == 3) ? winrow_to_orig(row) : row;
            #pragma unroll
            for (int nt = 0; nt < 4; nt++) {
                int c = (warp_n << 5) + (nt << 3) + (lc << 1);
                float2 bv = *(const float2*)(bias + n0 + c);
                float v0 = acc[mt][nt][h * 2 + 0] + bv.x;
                float v1 = acc[mt][nt][h * 2 + 1] + bv.y;
                if (MODE == 1) {
                    v0 = 0.5f * v0 * (1.0f + erff(v0 * 0.70710678118654752f));
                    v1 = 0.5f * v1 * (1.0f + erff(v1 * 0.70710678118654752f));
                }
                if (MODE <= 1) {
                    __half2* dst = (__half2*)((__half*)Cv + (size_t)orow * N + n0 + c);
                    *dst = __floats2half2_rn(v0, v1);
                } else {
                    size_t cb = (size_t)orow * N + n0 + c;
                    float2 rv = *(const float2*)(res + cb);
                    float2 o; o.x = v0 + rv.x; o.y = v1 + rv.y;
                    *(float2*)((float*)Cv + cb) = o;
                }
            }
        }
    }
}

// ---------------- attention: 128 threads per (window, head) ----------------
__global__ void __launch_bounds__(128, 6) attn_kernel(
    const __half* __restrict__ qkv, const float* __restrict__ bfused,
    __half* __restrict__ o)
{
    int bh   = blockIdx.x;
    int wi   = bh / NHEAD;
    int head = bh - wi * NHEAD;
    int w    = wi & 63;
    int tid  = threadIdx.x;
    int lane = tid & 31;
    int wid  = tid >> 5;           // 0..3
    int type = (((w >> 3) == 7) ? 2 : 0) + (((w & 7) == 7) ? 1 : 0);

    __shared__ float qs[49][36];
    __shared__ float ks[49][36];
    __shared__ float vs[49][36];
    __shared__ float S [49][49];

    size_t base = (size_t)wi * 49 * 1152 + head * 32;
    for (int e = tid; e < 196; e += 128) {
        int n = e >> 2, c = e & 3;
        const __half* src = qkv + base + (size_t)n * 1152 + (c << 3);
        uint4 qv = *(const uint4*)(src);
        uint4 kv = *(const uint4*)(src + 384);
        uint4 vv = *(const uint4*)(src + 768);
        const __half2* qh = (const __half2*)&qv;
        const __half2* kh = (const __half2*)&kv;
        const __half2* vh = (const __half2*)&vv;
        #pragma unroll
        for (int t = 0; t < 4; t++) {
            float2 fq = __half22float2(qh[t]);
            float2 fk = __half22float2(kh[t]);
            float2 fv = __half22float2(vh[t]);
            qs[n][(c << 3) + 2*t    ] = fq.x * SCALE;
            qs[n][(c << 3) + 2*t + 1] = fq.y * SCALE;
            ks[n][(c << 3) + 2*t    ] = fk.x;
            ks[n][(c << 3) + 2*t + 1] = fk.y;
            vs[n][(c << 3) + 2*t    ] = fv.x;
            vs[n][(c << 3) + 2*t + 1] = fv.y;
        }
    }
    __syncthreads();

    const float* Bf = bfused + (size_t)(type * NHEAD + head) * 2401;

    for (int i = wid; i < 49; i += 4) {
        float4 q[8];
        #pragma unroll
        for (int t = 0; t < 8; t++) q[t] = *(const float4*)&qs[i][t * 4];
        const float* Br = Bf + i * 49;

        float sv0, sv1;
        {
            int j = lane;
            float s = Br[j];
            #pragma unroll
            for (int t = 0; t < 8; t++) {
                float4 kv = *(const float4*)&ks[j][t * 4];
                s += q[t].x * kv.x + q[t].y * kv.y + q[t].z * kv.z + q[t].w * kv.w;
            }
            sv0 = s;
        }
        if (lane < 17) {
            int j = lane + 32;
            float s = Br[j];
            #pragma unroll
            for (int t = 0; t < 8; t++) {
                float4 kv = *(const float4*)&ks[j][t * 4];
                s += q[t].x * kv.x + q[t].y * kv.y + q[t].z * kv.z + q[t].w * kv.w;
            }
            sv1 = s;
        } else sv1 = -1e30f;

        float mx = fmaxf(sv0, sv1);
        #pragma unroll
        for (int off = 16; off; off >>= 1) mx = fmaxf(mx, __shfl_xor_sync(~0u, mx, off));
        float e0 = __expf(sv0 - mx);
        float e1 = (lane < 17) ? __expf(sv1 - mx) : 0.0f;
        float sm = e0 + e1;
        #pragma unroll
        for (int off = 16; off; off >>= 1) sm += __shfl_xor_sync(~0u, sm, off);
        float inv = 1.0f / sm;
        S[i][lane] = e0 * inv;
        if (lane < 17) S[i][lane + 32] = e1 * inv;
    }
    __syncthreads();

    size_t obase = (size_t)wi * 49 * 384 + head * 32;
    for (int task = tid; task < 49 * 8; task += 128) {
        int i = task >> 3, d4 = task & 7;
        float ax = 0.f, ay = 0.f, az = 0.f, aw = 0.f;
        #pragma unroll 7
        for (int j = 0; j < 49; j++) {
            float s = S[i][j];
            float4 v = *(const float4*)&vs[j][d4 * 4];
            ax += s * v.x; ay += s * v.y; az += s * v.z; aw += s * v.w;
        }
        __half2* op = (__half2*)&o[obase + (size_t)i * 384 + d4 * 4];
        op[0] = __floats2half2_rn(ax, ay);
        op[1] = __floats2half2_rn(az, aw);
    }
}

// ---------------- host launch ----------------------------------------------
extern "C" void kernel_launch(void* const* d_in, const int* in_sizes, int n_in,
                              void* d_out, int out_size)
{
    const float* x       = (const float*)d_in[0];
    const float* ln1_g   = (const float*)d_in[1];
    const float* ln1_b   = (const float*)d_in[2];
    const float* qkv_w   = (const float*)d_in[3];
    const float* qkv_b   = (const float*)d_in[4];
    const float* proj_w  = (const float*)d_in[5];
    const float* proj_b  = (const float*)d_in[6];
    const float* bias_tb = (const float*)d_in[7];
    const float* ln2_g   = (const float*)d_in[8];
    const float* ln2_b   = (const float*)d_in[9];
    const float* fc1_w   = (const float*)d_in[10];
    const float* fc1_b   = (const float*)d_in[11];
    const float* fc2_w   = (const float*)d_in[12];
    const float* fc2_b   = (const float*)d_in[13];
    float*       out     = (float*)d_out;

    __half *ph, *pqkv, *po, *py, *pu, *pwt;
    float  *pxa, *pbias;
    cudaGetSymbolAddress((void**)&ph,   g_h);
    cudaGetSymbolAddress((void**)&pqkv, g_qkv);
    cudaGetSymbolAddress((void**)&po,   g_o);
    cudaGetSymbolAddress((void**)&pxa,  g_xa);
    cudaGetSymbolAddress((void**)&py,   g_y);
    cudaGetSymbolAddress((void**)&pu,   g_u);
    cudaGetSymbolAddress((void**)&pwt,  g_wt);
    cudaGetSymbolAddress((void**)&pbias, g_bias);

    cudaFuncSetAttribute(tc_gemm<0>, cudaFuncAttributeMaxDynamicSharedMemorySize, SMEM_SZ);
    cudaFuncSetAttribute(tc_gemm<1>, cudaFuncAttributeMaxDynamicSharedMemorySize, SMEM_SZ);
    cudaFuncSetAttribute(tc_gemm<2>, cudaFuncAttributeMaxDynamicSharedMemorySize, SMEM_SZ);
    cudaFuncSetAttribute(tc_gemm<3>, cudaFuncAttributeMaxDynamicSharedMemorySize, SMEM_SZ);

    // 1. LN1 + shift + window gather -> fp16
    ln_kernel<1><<<TOK / 4, 128>>>(x, ln1_g, ln1_b, ph);

    // 0a. all weight transposes in one launch
    transpose_all<<<1728, 256>>>(qkv_w, proj_w, fc1_w, fc2_w, pwt);

    // 0b. fused bias+mask tables (4 types x 12 heads)
    prep_bias<<<4 * NHEAD, 256>>>(bias_tb, pbias);

    // 2. qkv GEMM [100352 x 1152], K=384 -> fp16
    tc_gemm<0><<<dim3(9, TOK / 128), 256, SMEM_SZ>>>(ph, pwt + WT_QKV, qkv_b, nullptr, pqkv, 1152, 384);

    // 3. windowed attention -> fp16
    attn_kernel<<<2048 * NHEAD, 128>>>(pqkv, pbias, po);

    // 4. proj GEMM + window-reverse scatter + residual(x) -> fp32 xa
    tc_gemm<3><<<dim3(3, TOK / 128), 256, SMEM_SZ>>>(po, pwt + WT_PROJ, proj_b, x, pxa, 384, 384);

    // 5. LN2 -> fp16
    ln_kernel<0><<<TOK / 4, 128>>>(pxa, ln2_g, ln2_b, py);

    // 6. fc1 GEMM + gelu, N=1536 -> fp16
    tc_gemm<1><<<dim3(12, TOK / 128), 256, SMEM_SZ>>>(py, pwt + WT_FC1, fc1_b, nullptr, pu, 1536, 384);

    // 7. fc2 GEMM + residual -> fp32 out, K=1536
    tc_gemm<2><<<dim3(3, TOK / 128), 256, SMEM_SZ>>>(pu, pwt + WT_FC2, fc2_b, pxa, out, 384, 1536);
}

// round 15
// speedup vs baseline: 1.7695x; 1.0051x over previous
#include <cuda_runtime.h>
#include <cuda_fp16.h>
#include <math.h>
#include <stdint.h>

// ---------------- problem constants ----------------
#define CDIM    384
#define NHEAD   12
#define TOK     100352        // 32*3136
#define EPS     1e-5f
#define SCALE   0.17677669529663687f  // 1/sqrt(32)

// ---------------- scratch (device globals; no allocations) ----------------
__device__ __half g_h  [(size_t)TOK * 384];
__device__ __half g_qkv[(size_t)TOK * 1152];
__device__ __half g_o  [(size_t)TOK * 384];
__device__ float  g_xa [(size_t)TOK * 384];   // residual stream stays fp32
__device__ __half g_y  [(size_t)TOK * 384];
__device__ __half g_u  [(size_t)TOK * 1536];
__device__ __half g_wt [1769472];             // transposed fp16 weights
__device__ float  g_bias[4 * NHEAD * 2401];   // fused rpb+mask per (type, head)

#define WT_QKV 0
#define WT_PROJ 442368
#define WT_FC1 589824
#define WT_FC2 1179648

// ---------------- small PTX helpers ----------------
__device__ __forceinline__ uint32_t smem_u32(const void* p){
    uint32_t a;
    asm("{ .reg .u64 t; cvta.to.shared.u64 t, %1; cvt.u32.u64 %0, t; }" : "=r"(a) : "l"(p));
    return a;
}
__device__ __forceinline__ void cp16(uint32_t d, const void* s){
    asm volatile("cp.async.cg.shared.global [%0], [%1], 16;" :: "r"(d), "l"(s));
}
__device__ __forceinline__ void cp_commit(){ asm volatile("cp.async.commit_group;"); }
__device__ __forceinline__ void cp_wait1(){ asm volatile("cp.async.wait_group 1;" ::: "memory"); }
__device__ __forceinline__ void cp_wait0(){ asm volatile("cp.async.wait_group 0;" ::: "memory"); }

// fp16 m16n8k16 mma, fp32 accumulate
__device__ __forceinline__ void mma16(float* d, uint32_t a0, uint32_t a1,
                                      uint32_t a2, uint32_t a3,
                                      uint32_t b0, uint32_t b1){
    asm volatile("mma.sync.aligned.m16n8k16.row.col.f32.f16.f16.f32 "
        "{%0,%1,%2,%3}, {%4,%5,%6,%7}, {%8,%9}, {%0,%1,%2,%3};"
        : "+f"(d[0]), "+f"(d[1]), "+f"(d[2]), "+f"(d[3])
        : "r"(a0), "r"(a1), "r"(a2), "r"(a3), "r"(b0), "r"(b1));
}

__device__ __forceinline__ void ldsm4(uint32_t& r0, uint32_t& r1,
                                      uint32_t& r2, uint32_t& r3, uint32_t addr){
    asm volatile("ldmatrix.sync.aligned.m8n8.x4.shared.b16 {%0,%1,%2,%3}, [%4];"
        : "=r"(r0), "=r"(r1), "=r"(r2), "=r"(r3) : "r"(addr));
}

// window-order row t <-> original-order row (self-inverse map)
__device__ __forceinline__ int winrow_to_orig(int t) {
    int b   = t / 3136;
    int rem = t - b * 3136;
    int w   = rem / 49;
    int n   = rem - w * 49;
    int wr = w >> 3, wc = w & 7;
    int r  = n / 7,  c  = n - r * 7;
    int gh = wr * 7 + r + 3; if (gh >= 56) gh -= 56;
    int gw = wc * 7 + c + 3; if (gw >= 56) gw -= 56;
    return b * 3136 + gh * 56 + gw;
}

// ---------------- LayerNorm -> fp16, warp-per-token, no smem/syncs ---------
template<int GATHER>
__global__ void __launch_bounds__(128) ln_kernel(
    const float* __restrict__ x, const float* __restrict__ g,
    const float* __restrict__ b, __half* __restrict__ out)
{
    int warp = threadIdx.x >> 5, lane = threadIdx.x & 31;
    int t    = (blockIdx.x << 2) + warp;
    int src  = GATHER ? winrow_to_orig(t) : t;

    const float4* xr = (const float4*)(x + (size_t)src * CDIM) + lane * 3;
    float4 v0 = xr[0], v1 = xr[1], v2 = xr[2];

    float s  = v0.x + v0.y + v0.z + v0.w + v1.x + v1.y + v1.z + v1.w
             + v2.x + v2.y + v2.z + v2.w;
    float sq = v0.x*v0.x + v0.y*v0.y + v0.z*v0.z + v0.w*v0.w
             + v1.x*v1.x + v1.y*v1.y + v1.z*v1.z + v1.w*v1.w
             + v2.x*v2.x + v2.y*v2.y + v2.z*v2.z + v2.w*v2.w;
    #pragma unroll
    for (int off = 16; off; off >>= 1) {
        s  += __shfl_xor_sync(~0u, s,  off);
        sq += __shfl_xor_sync(~0u, sq, off);
    }
    float mean = s * (1.0f / CDIM);
    float var  = sq * (1.0f / CDIM) - mean * mean;
    float inv  = rsqrtf(var + EPS);

    const float4* gp = (const float4*)g + lane * 3;
    const float4* bp = (const float4*)b + lane * 3;
    float4 g0 = gp[0], g1 = gp[1], g2 = gp[2];
    float4 b0 = bp[0], b1 = bp[1], b2 = bp[2];

    __half2* op = (__half2*)(out + (size_t)t * CDIM + lane * 12);
    op[0] = __floats2half2_rn((v0.x - mean) * inv * g0.x + b0.x, (v0.y - mean) * inv * g0.y + b0.y);
    op[1] = __floats2half2_rn((v0.z - mean) * inv * g0.z + b0.z, (v0.w - mean) * inv * g0.w + b0.w);
    op[2] = __floats2half2_rn((v1.x - mean) * inv * g1.x + b1.x, (v1.y - mean) * inv * g1.y + b1.y);
    op[3] = __floats2half2_rn((v1.z - mean) * inv * g1.z + b1.z, (v1.w - mean) * inv * g1.w + b1.w);
    op[4] = __floats2half2_rn((v2.x - mean) * inv * g2.x + b2.x, (v2.y - mean) * inv * g2.y + b2.y);
    op[5] = __floats2half2_rn((v2.z - mean) * inv * g2.z + b2.z, (v2.w - mean) * inv * g2.w + b2.w);
}

// ---------------- all 4 weight transposes in ONE launch ---------------------
__global__ void __launch_bounds__(256) transpose_all(
    const float* __restrict__ qkv_w, const float* __restrict__ proj_w,
    const float* __restrict__ fc1_w, const float* __restrict__ fc2_w,
    __half* __restrict__ wt)
{
    __shared__ float tile[32][33];
    int bid = blockIdx.x;
    const float* in; __half* out; int K, N, tIdx;
    if (bid < 432)       { in = qkv_w;  out = wt + WT_QKV;  K = 384;  N = 1152; tIdx = bid; }
    else if (bid < 576)  { in = proj_w; out = wt + WT_PROJ; K = 384;  N = 384;  tIdx = bid - 432; }
    else if (bid < 1152) { in = fc1_w;  out = wt + WT_FC1;  K = 384;  N = 1536; tIdx = bid - 576; }
    else                 { in = fc2_w;  out = wt + WT_FC2;  K = 1536; N = 384;  tIdx = bid - 1152; }
    int ntx = N >> 5;
    int by = tIdx / ntx, bx = tIdx - by * ntx;
    int k0 = by * 32, n0 = bx * 32;
    int tx = threadIdx.x & 31, ty = threadIdx.x >> 5;
    #pragma unroll
    for (int i = ty; i < 32; i += 8)
        tile[i][tx] = in[(size_t)(k0 + i) * N + n0 + tx];
    __syncthreads();
    #pragma unroll
    for (int i = ty; i < 32; i += 8)
        out[(size_t)(n0 + i) * K + k0 + tx] = __float2half(tile[tx][i]);
}

// ---------------- fused rel-pos bias + shifted-window mask -----------------
__global__ void __launch_bounds__(256) prep_bias(
    const float* __restrict__ bias_table, float* __restrict__ gb)
{
    int type = blockIdx.x / NHEAD, head = blockIdx.x - type * NHEAD;
    int rowB = type >> 1, colB = type & 1;
    for (int e = threadIdx.x; e < 2401; e += 256) {
        int i = e / 49, j = e - i * 49;
        int ih = i / 7, iw = i - ih * 7;
        int jh = j / 7, jw = j - jh * 7;
        float v = bias_table[((ih - jh + 6) * 13 + (iw - jw + 6)) * NHEAD + head];
        int li = (rowB ? (ih < 4 ? 1 : 2) : 0) * 3 + (colB ? (iw < 4 ? 1 : 2) : 0);
        int lj = (rowB ? (jh < 4 ? 1 : 2) : 0) * 3 + (colB ? (jw < 4 ? 1 : 2) : 0);
        if (li != lj) v -= 100.0f;
        gb[blockIdx.x * 2401 + e] = v;
    }
}

// ---------------- FP16 mma.sync GEMM ----------------------------------------
// 128x128 CTA tile, 4 warps in 2x2 grid of 64x64 warp tiles, K staged by 64,
// 3-stage cp.async pipeline, ONE barrier per stage, ldmatrix fragments.
// 128 threads, launch_bounds(128,2) -> 256-reg budget (acc=128 regs fits).
#define PITCH_B 144      // bytes per row (72 halves)
#define STG_B   36864    // bytes per stage
#define SMEM_SZ 110592   // 3 stages

template<int MODE>
__global__ void __launch_bounds__(128, 2) tc_gemm(
    const __half* __restrict__ A, const __half* __restrict__ Bt,
    const float* __restrict__ bias, const float* __restrict__ res,
    void* __restrict__ Cv, int N, int K)
{
    extern __shared__ __align__(16) char smem[];
    int tid  = threadIdx.x;
    int lane = tid & 31;
    int wid  = tid >> 5;           // 0..3
    int warp_m = wid >> 1;         // 2 x 64 rows
    int warp_n = wid & 1;          // 2 x 64 cols
    int m0 = blockIdx.y << 7, n0 = blockIdx.x << 7;

    const __half* Arow = A  + (size_t)m0 * K;
    const __half* Brow = Bt + (size_t)n0 * K;
    const int nst = K >> 6;

    uint32_t sbase = smem_u32(smem);

    int ldrow = tid >> 3;          // 0..15 (p adds 16)
    int ldc   = tid & 7;           // 16B chunk within 64-half row

    auto issue_stage = [&](int s, int buf) {
        int kt = s << 6;
        uint32_t bA = sbase + (uint32_t)buf * STG_B;
        uint32_t bB = bA + 18432;
        #pragma unroll
        for (int p = 0; p < 8; ++p) {
            int row = ldrow + (p << 4);
            uint32_t doff = (uint32_t)row * PITCH_B + (uint32_t)(ldc << 4);
            cp16(bA + doff, Arow + (size_t)row * K + kt + (ldc << 3));
            cp16(bB + doff, Brow + (size_t)row * K + kt + (ldc << 3));
        }
        cp_commit();
    };

    float acc[4][8][4];
    #pragma unroll
    for (int i = 0; i < 4; i++)
        #pragma unroll
        for (int j = 0; j < 8; j++)
            #pragma unroll
            for (int r = 0; r < 4; r++) acc[i][j][r] = 0.0f;

    issue_stage(0, 0);
    issue_stage(1, 1);

    int lr = lane >> 2;
    int lc = lane & 3;

    uint32_t a_row = (uint32_t)((warp_m << 6) + (lane & 15));
    uint32_t a_off = a_row * PITCH_B + ((uint32_t)(lane >> 4) << 4);
    uint32_t b_row = (uint32_t)((warp_n << 6) + (lane & 7) + (((lane >> 4) & 1) << 3));
    uint32_t b_off = b_row * PITCH_B + (((uint32_t)(lane >> 3) & 1) << 4);

    for (int s = 0; s < nst; ++s) {
        int buf = s % 3;
        if (s == nst - 1) cp_wait0(); else cp_wait1();
        __syncthreads();   // stage s visible; all threads done computing s-1
        if (s + 2 < nst) issue_stage(s + 2, (s + 2) % 3);

        uint32_t bA = sbase + (uint32_t)buf * STG_B;
        uint32_t bB = bA + 18432;

        #pragma unroll
        for (int kk = 0; kk < 4; kk++) {       // four k16 chunks, 32B apart
            uint32_t a[4][4];
            #pragma unroll
            for (int mt = 0; mt < 4; mt++)
                ldsm4(a[mt][0], a[mt][1], a[mt][2], a[mt][3],
                      bA + a_off + (uint32_t)(mt * 16 * PITCH_B) + (kk << 5));
            uint32_t b[4][4];
            #pragma unroll
            for (int bt = 0; bt < 4; bt++)
                ldsm4(b[bt][0], b[bt][1], b[bt][2], b[bt][3],
                      bB + b_off + (uint32_t)(bt * 16 * PITCH_B) + (kk << 5));
            #pragma unroll
            for (int mt = 0; mt < 4; mt++)
                #pragma unroll
                for (int bt = 0; bt < 4; bt++) {
                    mma16(acc[mt][bt * 2 + 0], a[mt][0], a[mt][1], a[mt][2], a[mt][3],
                          b[bt][0], b[bt][1]);
                    mma16(acc[mt][bt * 2 + 1], a[mt][0], a[mt][1], a[mt][2], a[mt][3],
                          b[bt][2], b[bt][3]);
                }
        }
    }

    // ---- epilogue ----
    #pragma unroll
    for (int mt = 0; mt < 4; mt++) {
        #pragma unroll
        for (int h = 0; h < 2; h++) {
            int row  = m0 + (warp_m << 6) + (mt << 4) + lr + (h << 3);
            int orow = (MODE == 3) ? winrow_to_orig(row) : row;
            #pragma unroll
            for (int nt = 0; nt < 8; nt++) {
                int c = (warp_n << 6) + (nt << 3) + (lc << 1);
                float2 bv = *(const float2*)(bias + n0 + c);
                float v0 = acc[mt][nt][h * 2 + 0] + bv.x;
                float v1 = acc[mt][nt][h * 2 + 1] + bv.y;
                if (MODE == 1) {
                    v0 = 0.5f * v0 * (1.0f + erff(v0 * 0.70710678118654752f));
                    v1 = 0.5f * v1 * (1.0f + erff(v1 * 0.70710678118654752f));
                }
                if (MODE <= 1) {
                    __half2* dst = (__half2*)((__half*)Cv + (size_t)orow * N + n0 + c);
                    *dst = __floats2half2_rn(v0, v1);
                } else {
                    size_t cb = (size_t)orow * N + n0 + c;
                    float2 rv = *(const float2*)(res + cb);
                    float2 o; o.x = v0 + rv.x; o.y = v1 + rv.y;
                    *(float2*)((float*)Cv + cb) = o;
                }
            }
        }
    }
}

// ---------------- attention: 128 threads per (window, head) ----------------
__global__ void __launch_bounds__(128, 6) attn_kernel(
    const __half* __restrict__ qkv, const float* __restrict__ bfused,
    __half* __restrict__ o)
{
    int bh   = blockIdx.x;
    int wi   = bh / NHEAD;
    int head = bh - wi * NHEAD;
    int w    = wi & 63;
    int tid  = threadIdx.x;
    int lane = tid & 31;
    int wid  = tid >> 5;           // 0..3
    int type = (((w >> 3) == 7) ? 2 : 0) + (((w & 7) == 7) ? 1 : 0);

    __shared__ float qs[49][36];
    __shared__ float ks[49][36];
    __shared__ float vs[49][36];
    __shared__ float S [49][49];

    size_t base = (size_t)wi * 49 * 1152 + head * 32;
    for (int e = tid; e < 196; e += 128) {
        int n = e >> 2, c = e & 3;
        const __half* src = qkv + base + (size_t)n * 1152 + (c << 3);
        uint4 qv = *(const uint4*)(src);
        uint4 kv = *(const uint4*)(src + 384);
        uint4 vv = *(const uint4*)(src + 768);
        const __half2* qh = (const __half2*)&qv;
        const __half2* kh = (const __half2*)&kv;
        const __half2* vh = (const __half2*)&vv;
        #pragma unroll
        for (int t = 0; t < 4; t++) {
            float2 fq = __half22float2(qh[t]);
            float2 fk = __half22float2(kh[t]);
            float2 fv = __half22float2(vh[t]);
            qs[n][(c << 3) + 2*t    ] = fq.x * SCALE;
            qs[n][(c << 3) + 2*t + 1] = fq.y * SCALE;
            ks[n][(c << 3) + 2*t    ] = fk.x;
            ks[n][(c << 3) + 2*t + 1] = fk.y;
            vs[n][(c << 3) + 2*t    ] = fv.x;
            vs[n][(c << 3) + 2*t + 1] = fv.y;
        }
    }
    __syncthreads();

    const float* Bf = bfused + (size_t)(type * NHEAD + head) * 2401;

    for (int i = wid; i < 49; i += 4) {
        float4 q[8];
        #pragma unroll
        for (int t = 0; t < 8; t++) q[t] = *(const float4*)&qs[i][t * 4];
        const float* Br = Bf + i * 49;

        float sv0, sv1;
        {
            int j = lane;
            float s = Br[j];
            #pragma unroll
            for (int t = 0; t < 8; t++) {
                float4 kv = *(const float4*)&ks[j][t * 4];
                s += q[t].x * kv.x + q[t].y * kv.y + q[t].z * kv.z + q[t].w * kv.w;
            }
            sv0 = s;
        }
        if (lane < 17) {
            int j = lane + 32;
            float s = Br[j];
            #pragma unroll
            for (int t = 0; t < 8; t++) {
                float4 kv = *(const float4*)&ks[j][t * 4];
                s += q[t].x * kv.x + q[t].y * kv.y + q[t].z * kv.z + q[t].w * kv.w;
            }
            sv1 = s;
        } else sv1 = -1e30f;

        float mx = fmaxf(sv0, sv1);
        #pragma unroll
        for (int off = 16; off; off >>= 1) mx = fmaxf(mx, __shfl_xor_sync(~0u, mx, off));
        float e0 = __expf(sv0 - mx);
        float e1 = (lane < 17) ? __expf(sv1 - mx) : 0.0f;
        float sm = e0 + e1;
        #pragma unroll
        for (int off = 16; off; off >>= 1) sm += __shfl_xor_sync(~0u, sm, off);
        float inv = 1.0f / sm;
        S[i][lane] = e0 * inv;
        if (lane < 17) S[i][lane + 32] = e1 * inv;
    }
    __syncthreads();

    size_t obase = (size_t)wi * 49 * 384 + head * 32;
    for (int task = tid; task < 49 * 8; task += 128) {
        int i = task >> 3, d4 = task & 7;
        float ax = 0.f, ay = 0.f, az = 0.f, aw = 0.f;
        #pragma unroll 7
        for (int j = 0; j < 49; j++) {
            float s = S[i][j];
            float4 v = *(const float4*)&vs[j][d4 * 4];
            ax += s * v.x; ay += s * v.y; az += s * v.z; aw += s * v.w;
        }
        __half2* op = (__half2*)&o[obase + (size_t)i * 384 + d4 * 4];
        op[0] = __floats2half2_rn(ax, ay);
        op[1] = __floats2half2_rn(az, aw);
    }
}

// ---------------- host launch ----------------------------------------------
extern "C" void kernel_launch(void* const* d_in, const int* in_sizes, int n_in,
                              void* d_out, int out_size)
{
    const float* x       = (const float*)d_in[0];
    const float* ln1_g   = (const float*)d_in[1];
    const float* ln1_b   = (const float*)d_in[2];
    const float* qkv_w   = (const float*)d_in[3];
    const float* qkv_b   = (const float*)d_in[4];
    const float* proj_w  = (const float*)d_in[5];
    const float* proj_b  = (const float*)d_in[6];
    const float* bias_tb = (const float*)d_in[7];
    const float* ln2_g   = (const float*)d_in[8];
    const float* ln2_b   = (const float*)d_in[9];
    const float* fc1_w   = (const float*)d_in[10];
    const float* fc1_b   = (const float*)d_in[11];
    const float* fc2_w   = (const float*)d_in[12];
    const float* fc2_b   = (const float*)d_in[13];
    float*       out     = (float*)d_out;

    __half *ph, *pqkv, *po, *py, *pu, *pwt;
    float  *pxa, *pbias;
    cudaGetSymbolAddress((void**)&ph,   g_h);
    cudaGetSymbolAddress((void**)&pqkv, g_qkv);
    cudaGetSymbolAddress((void**)&po,   g_o);
    cudaGetSymbolAddress((void**)&pxa,  g_xa);
    cudaGetSymbolAddress((void**)&py,   g_y);
    cudaGetSymbolAddress((void**)&pu,   g_u);
    cudaGetSymbolAddress((void**)&pwt,  g_wt);
    cudaGetSymbolAddress((void**)&pbias, g_bias);

    cudaFuncSetAttribute(tc_gemm<0>, cudaFuncAttributeMaxDynamicSharedMemorySize, SMEM_SZ);
    cudaFuncSetAttribute(tc_gemm<1>, cudaFuncAttributeMaxDynamicSharedMemorySize, SMEM_SZ);
    cudaFuncSetAttribute(tc_gemm<2>, cudaFuncAttributeMaxDynamicSharedMemorySize, SMEM_SZ);
    cudaFuncSetAttribute(tc_gemm<3>, cudaFuncAttributeMaxDynamicSharedMemorySize, SMEM_SZ);

    // 1. LN1 + shift + window gather -> fp16
    ln_kernel<1><<<TOK / 4, 128>>>(x, ln1_g, ln1_b, ph);

    // 0a. all weight transposes in one launch
    transpose_all<<<1728, 256>>>(qkv_w, proj_w, fc1_w, fc2_w, pwt);

    // 0b. fused bias+mask tables (4 types x 12 heads)
    prep_bias<<<4 * NHEAD, 256>>>(bias_tb, pbias);

    // 2. qkv GEMM [100352 x 1152], K=384 -> fp16
    tc_gemm<0><<<dim3(9, TOK / 128), 128, SMEM_SZ>>>(ph, pwt + WT_QKV, qkv_b, nullptr, pqkv, 1152, 384);

    // 3. windowed attention -> fp16
    attn_kernel<<<2048 * NHEAD, 128>>>(pqkv, pbias, po);

    // 4. proj GEMM + window-reverse scatter + residual(x) -> fp32 xa
    tc_gemm<3><<<dim3(3, TOK / 128), 128, SMEM_SZ>>>(po, pwt + WT_PROJ, proj_b, x, pxa, 384, 384);

    // 5. LN2 -> fp16
    ln_kernel<0><<<TOK / 4, 128>>>(pxa, ln2_g, ln2_b, py);

    // 6. fc1 GEMM + gelu, N=1536 -> fp16
    tc_gemm<1><<<dim3(12, TOK / 128), 128, SMEM_SZ>>>(py, pwt + WT_FC1, fc1_b, nullptr, pu, 1536, 384);

    // 7. fc2 GEMM + residual -> fp32 out, K=1536
    tc_gemm<2><<<dim3(3, TOK / 128), 128, SMEM_SZ>>>(pu, pwt + WT_FC2, fc2_b, pxa, out, 384, 1536);
}